// round 4
// baseline (speedup 1.0000x reference)
#include <cuda_runtime.h>
#include <math.h>

// Problem constants (fixed shapes for this dataset entry)
#define BATCH   32
#define NW      16
#define BW      512            // BATCH*NW sequences
#define EMB     256
#define HID     512
#define OUTD    64
#define TSTEPS  128
#define MTOT    (BW * TSTEPS)  // 65536 MLP rows

// ---------------------------------------------------------------------------
// Scratch (device globals; no dynamic allocation allowed)
//   g_hT : hidden states, TRANSPOSED layout [t][unit][row]; t=0 is h0.
//   g_act1/g_act2 : MLP activation ping-pong, m-major with m = t*512 + row.
// ---------------------------------------------------------------------------
__device__ float g_hT[(TSTEPS + 1)][EMB][BW];          // ~67.6 MB
__device__ float g_act1[(size_t)MTOT * HID];            // 134 MB
__device__ float g_act2[(size_t)MTOT * HID];            // 134 MB

// ---------------------------------------------------------------------------
// Kernel 1: embedding  h0[u][row] = sum_k concat(z_t,z_g)[row][k] * w_emb[u][k]
// One block per row (512 blocks), one thread per output unit.
// w_emb is 131 KB -> L1/L2 resident after first touch.
// ---------------------------------------------------------------------------
__global__ void embed_kernel(const float* __restrict__ z_t,
                             const float* __restrict__ z_g,
                             const float* __restrict__ w_emb) {
    int row = blockIdx.x;       // 0..511
    int u   = threadIdx.x;      // 0..255
    __shared__ float zs[128];
    if (u < 64)        zs[u] = z_t[row * 64 + u];
    else if (u < 128)  zs[u] = z_g[(row >> 4) * 64 + (u & 63)];
    __syncthreads();
    const float* wr = w_emb + u * 128;
    float acc = 0.f;
#pragma unroll 16
    for (int k = 0; k < 128; ++k) acc = fmaf(zs[k], wr[k], acc);
    g_hT[0][u][row] = acc;
}

// ---------------------------------------------------------------------------
// Kernel 2: one fused GRU step.
// Grid (16 unit-blocks x 8 row-blocks) = 128 CTAs, 256 threads.
// CTA tile: 16 hidden units x 64 rows; all 3 gates computed locally so the
// nonlinear update fuses into the GEMM epilogue (one launch per step).
// smem: h_prev tile [256 k][64 rows] (64KB) + W slice [16u][257pad][r,z,n,pad]
// (~66KB). Pad 257 keeps the per-k W LDS.128 bank-conflict-free.
// ---------------------------------------------------------------------------
#define GRU_SMEM_FLOATS (256 * 64 + 16 * 257 * 4)
#define GRU_SMEM_BYTES  (GRU_SMEM_FLOATS * 4)

__global__ __launch_bounds__(256) void gru_step_kernel(
        const float* __restrict__ w_hh,
        const float* __restrict__ b_ih,
        const float* __restrict__ b_hh,
        int t) {
    extern __shared__ float sm[];
    float*  hs  = sm;                     // [256][64]
    float*  ws  = sm + 256 * 64;          // [16][257][4]
    float4* hs4 = (float4*)hs;
    float4* ws4 = (float4*)ws;

    const int u0  = blockIdx.x * 16;      // unit block
    const int r0  = blockIdx.y * 64;      // row block
    const int tid = threadIdx.x;

    // ---- load h_prev tile (coalesced float4, rows contiguous) ----
    const float* hprev = &g_hT[t - 1][0][0];
#pragma unroll
    for (int i = tid; i < 4096; i += 256) {
        hs4[i] = *(const float4*)(hprev + (i >> 4) * BW + r0 + (i & 15) * 4);
    }
    // ---- load W slice: rows {g*256 + u0+ux} for g in {r,z,n}, ux 0..15 ----
#pragma unroll
    for (int i = tid; i < 3072; i += 256) {
        int rr = i >> 6;                  // 0..47
        int k4 = i & 63;                  // float4 index along K
        int g  = rr >> 4, ux = rr & 15;
        float4 v = *(const float4*)(w_hh + (g * 256 + u0 + ux) * 256 + k4 * 4);
        int base = (ux * 257 + k4 * 4) * 4 + g;
        ws[base]      = v.x;
        ws[base + 4]  = v.y;
        ws[base + 8]  = v.z;
        ws[base + 12] = v.w;
    }
    __syncthreads();

    // ---- compute: thread = (unit ux, row-quad ry); 4 rows x 3 gates ----
    const int ux = tid & 15;
    const int ry = tid >> 4;              // 0..15 -> rows r0 + ry*4 .. +3
    const int j  = u0 + ux;               // global hidden unit

    float accr[4], accz[4], accn[4];
    const float bhr = b_hh[j], bhz = b_hh[EMB + j], bhn = b_hh[2 * EMB + j];
#pragma unroll
    for (int i = 0; i < 4; ++i) { accr[i] = bhr; accz[i] = bhz; accn[i] = bhn; }

    const int wb = ux * 257;
#pragma unroll 8
    for (int k = 0; k < 256; ++k) {
        float4 h4 = hs4[k * 16 + ry];     // 4 rows of h_prev at unit k
        float4 w4 = ws4[wb + k];          // (w_r, w_z, w_n, pad) for unit j
        accr[0] = fmaf(h4.x, w4.x, accr[0]);
        accr[1] = fmaf(h4.y, w4.x, accr[1]);
        accr[2] = fmaf(h4.z, w4.x, accr[2]);
        accr[3] = fmaf(h4.w, w4.x, accr[3]);
        accz[0] = fmaf(h4.x, w4.y, accz[0]);
        accz[1] = fmaf(h4.y, w4.y, accz[1]);
        accz[2] = fmaf(h4.z, w4.y, accz[2]);
        accz[3] = fmaf(h4.w, w4.y, accz[3]);
        accn[0] = fmaf(h4.x, w4.z, accn[0]);
        accn[1] = fmaf(h4.y, w4.z, accn[1]);
        accn[2] = fmaf(h4.z, w4.z, accn[2]);
        accn[3] = fmaf(h4.w, w4.z, accn[3]);
    }

    // ---- fused gate update (PyTorch GRU with zero input) ----
    const float bir = b_ih[j], biz = b_ih[EMB + j], bin = b_ih[2 * EMB + j];
    float4 hp = hs4[j * 16 + ry];         // h_prev[j][rows] (j is also a k idx)
    float hpv[4] = {hp.x, hp.y, hp.z, hp.w};
    float outv[4];
#pragma unroll
    for (int i = 0; i < 4; ++i) {
        float r = 1.f / (1.f + expf(-(bir + accr[i])));
        float z = 1.f / (1.f + expf(-(biz + accz[i])));
        float n = tanhf(bin + r * accn[i]);
        outv[i] = (1.f - z) * n + z * hpv[i];
    }
    *(float4*)(&g_hT[t][j][r0 + ry * 4]) =
        make_float4(outv[0], outv[1], outv[2], outv[3]);
}

// ---------------------------------------------------------------------------
// Kernel 3: generic fp32 GEMM  C = act(A @ Wt^T + bias)
//   Wt: torch layout [N][K] row-major.
//   ATRANS: A element (m,k) read from g_hT-style layout base[(m>>9)*EMB*BW
//           + k*BW + (m&511)]  (layer 1 input, zero-cost "transpose").
//   SCATTER: mu head writes out[((m&511)*T + (m>>9))*64 + n].
// Tile: BM=128 x BN x BK=16, 256 threads, per-thread 8 x TN outputs.
// ---------------------------------------------------------------------------
template <int BN, int TN, bool ATRANS, bool DOELU, bool SCATTER>
__global__ __launch_bounds__(256) void gemm_kernel(
        const float* __restrict__ A,
        const float* __restrict__ Wt,
        const float* __restrict__ bias,
        float* __restrict__ C,
        int K, int N) {
    constexpr int BM = 128, BK = 16;
    constexpr int WS  = BN + 4;           // padded W-tile stride (floats)
    constexpr int WS4 = WS / 4;
    __shared__ float4 As4[BK * BM / 4];   // [16][32] float4  = [k][m]
    __shared__ float4 Ws4s[BK * WS4];     // [16][WS4] float4 = [k][n]
    float* As = (float*)As4;
    float* Ws = (float*)Ws4s;

    const int tid = threadIdx.x;
    const int tx  = tid & 15;             // n group
    const int ty  = tid >> 4;             // m group
    const int bn  = blockIdx.x * BN;
    const int bm  = blockIdx.y * BM;

    const float* Abase = A;
    if (ATRANS) Abase = A + (size_t)(bm >> 9) * (EMB * BW) + (bm & 511);

    float acc[8][TN];
#pragma unroll
    for (int i = 0; i < 8; ++i)
#pragma unroll
        for (int jj = 0; jj < TN; ++jj) acc[i][jj] = 0.f;

    for (int k0 = 0; k0 < K; k0 += BK) {
        // -- load A tile --
        if (ATRANS) {
#pragma unroll
            for (int i = tid; i < 512; i += 256) {
                int k = i >> 5, r4 = i & 31;
                As4[k * 32 + r4] =
                    *(const float4*)(Abase + (size_t)(k0 + k) * BW + r4 * 4);
            }
        } else {
#pragma unroll
            for (int i = tid; i < 512; i += 256) {
                int row = i >> 2, kq = i & 3;
                float4 v = *(const float4*)(A + (size_t)(bm + row) * K + k0 + kq * 4);
                As[(kq * 4 + 0) * BM + row] = v.x;
                As[(kq * 4 + 1) * BM + row] = v.y;
                As[(kq * 4 + 2) * BM + row] = v.z;
                As[(kq * 4 + 3) * BM + row] = v.w;
            }
        }
        // -- load W tile (transpose into [k][n]) --
#pragma unroll
        for (int i = tid; i < BN * 4; i += 256) {
            int n = i >> 2, kq = i & 3;
            float4 v = *(const float4*)(Wt + (size_t)(bn + n) * K + k0 + kq * 4);
            Ws[(kq * 4 + 0) * WS + n] = v.x;
            Ws[(kq * 4 + 1) * WS + n] = v.y;
            Ws[(kq * 4 + 2) * WS + n] = v.z;
            Ws[(kq * 4 + 3) * WS + n] = v.w;
        }
        __syncthreads();

#pragma unroll
        for (int k = 0; k < BK; ++k) {
            float a[8];
            float4 a0 = As4[k * 32 + ty * 2];
            float4 a1 = As4[k * 32 + ty * 2 + 1];
            a[0] = a0.x; a[1] = a0.y; a[2] = a0.z; a[3] = a0.w;
            a[4] = a1.x; a[5] = a1.y; a[6] = a1.z; a[7] = a1.w;
            float b[TN];
            if (TN == 8) {
                float4 b0 = Ws4s[k * WS4 + tx * 2];
                float4 b1 = Ws4s[k * WS4 + tx * 2 + 1];
                b[0] = b0.x; b[1] = b0.y; b[2] = b0.z; b[3] = b0.w;
                b[4] = b1.x; b[5] = b1.y; b[6] = b1.z; b[7] = b1.w;
            } else {
                float4 b0 = Ws4s[k * WS4 + tx];
                b[0] = b0.x; b[1] = b0.y; b[2] = b0.z; b[3] = b0.w;
            }
#pragma unroll
            for (int i = 0; i < 8; ++i)
#pragma unroll
                for (int jj = 0; jj < TN; ++jj)
                    acc[i][jj] = fmaf(a[i], b[jj], acc[i][jj]);
        }
        __syncthreads();
    }

    // -- epilogue --
    float bv[TN];
#pragma unroll
    for (int jj = 0; jj < TN; ++jj) bv[jj] = bias[bn + tx * TN + jj];
#pragma unroll
    for (int i = 0; i < 8; ++i) {
        int m = bm + ty * 8 + i;
        float o[TN];
#pragma unroll
        for (int jj = 0; jj < TN; ++jj) {
            float v = acc[i][jj] + bv[jj];
            if (DOELU) v = (v > 0.f) ? v : expm1f(v);
            o[jj] = v;
        }
        float* dst;
        if (SCATTER) {
            int rowbw = m & 511, tt = m >> 9;
            dst = C + ((size_t)(rowbw * TSTEPS + tt)) * OUTD + tx * TN;
        } else {
            dst = C + (size_t)m * N + bn + tx * TN;
        }
#pragma unroll
        for (int j4 = 0; j4 < TN; j4 += 4)
            *(float4*)(dst + j4) = make_float4(o[j4], o[j4 + 1], o[j4 + 2], o[j4 + 3]);
    }
}

// ---------------------------------------------------------------------------
// Host launcher (graph-capturable: kernel launches only)
// ---------------------------------------------------------------------------
extern "C" void kernel_launch(void* const* d_in, const int* in_sizes, int n_in,
                              void* d_out, int out_size) {
    (void)in_sizes; (void)n_in; (void)out_size;
    const float* z_t   = (const float*)d_in[0];
    const float* z_g   = (const float*)d_in[1];
    const float* w_emb = (const float*)d_in[2];
    const float* w_hh  = (const float*)d_in[3];
    const float* b_ih  = (const float*)d_in[4];
    const float* b_hh  = (const float*)d_in[5];
    const float* w1    = (const float*)d_in[6];
    const float* b1    = (const float*)d_in[7];
    const float* w2    = (const float*)d_in[8];
    const float* b2    = (const float*)d_in[9];
    const float* w3    = (const float*)d_in[10];
    const float* b3    = (const float*)d_in[11];
    const float* muw   = (const float*)d_in[12];
    const float* mub   = (const float*)d_in[13];
    float* out = (float*)d_out;

    float *hT, *act1, *act2;
    cudaGetSymbolAddress((void**)&hT,   g_hT);
    cudaGetSymbolAddress((void**)&act1, g_act1);
    cudaGetSymbolAddress((void**)&act2, g_act2);

    cudaFuncSetAttribute(gru_step_kernel,
                         cudaFuncAttributeMaxDynamicSharedMemorySize,
                         GRU_SMEM_BYTES);

    // 1) embedding -> h0 (transposed layout)
    embed_kernel<<<512, 256>>>(z_t, z_g, w_emb);

    // 2) 128 sequential fused GRU steps
    for (int t = 1; t <= TSTEPS; ++t) {
        gru_step_kernel<<<dim3(16, 8), 256, GRU_SMEM_BYTES>>>(w_hh, b_ih, b_hh, t);
    }

    // 3) MLP (layer1 reads hT[1..128] directly in transposed layout)
    const float* h_seq = hT + (size_t)EMB * BW;   // &g_hT[1][0][0]
    gemm_kernel<128, 8, true,  true,  false>
        <<<dim3(HID / 128, MTOT / 128), 256>>>(h_seq, w1, b1, act1, EMB, HID);
    gemm_kernel<128, 8, false, true,  false>
        <<<dim3(HID / 128, MTOT / 128), 256>>>(act1, w2, b2, act2, HID, HID);
    gemm_kernel<128, 8, false, true,  false>
        <<<dim3(HID / 128, MTOT / 128), 256>>>(act2, w3, b3, act1, HID, HID);

    // 4) mu head with output scatter to (B, W*T, OUT) ordering
    gemm_kernel<64, 4, false, false, true>
        <<<dim3(1, MTOT / 128), 256>>>(act1, muw, mub, out, HID, OUTD);
}

// round 5
// speedup vs baseline: 1.4297x; 1.4297x over previous
#include <cuda_runtime.h>
#include <math.h>

// Problem constants
#define BATCH   32
#define NW      16
#define BW      512
#define EMB     256
#define HID     512
#define OUTD    64
#define TSTEPS  128
#define MTOT    (BW * TSTEPS)

// ---------------------------------------------------------------------------
// Scratch
// ---------------------------------------------------------------------------
__device__ float g_hT[(TSTEPS + 1)][EMB][BW];           // [t][unit][row]
__device__ float g_act1[(size_t)MTOT * HID];
__device__ float g_act2[(size_t)MTOT * HID];
__device__ unsigned int g_bar;                          // grid barrier counter

// ---------------------------------------------------------------------------
// f32x2 helpers (FFMA2 — only reachable via PTX fma.rn.f32x2)
// ---------------------------------------------------------------------------
typedef unsigned long long ull;
__device__ __forceinline__ ull pack2(float x, float y) {
    ull r; asm("mov.b64 %0, {%1,%2};" : "=l"(r) : "f"(x), "f"(y)); return r;
}
__device__ __forceinline__ void ffma2(ull& d, ull a, ull b) {
    asm("fma.rn.f32x2 %0, %1, %2, %0;" : "+l"(d) : "l"(a), "l"(b));
}
__device__ __forceinline__ float2 unpk(ull v) {
    float2 f; asm("mov.b64 {%0,%1}, %2;" : "=f"(f.x), "=f"(f.y) : "l"(v)); return f;
}
__device__ __forceinline__ unsigned smaddr(const void* p) {
    unsigned r;
    asm("{.reg .u64 t; cvta.to.shared.u64 t, %1; cvt.u32.u64 %0, t;}"
        : "=r"(r) : "l"(p));
    return r;
}
#define CP16(ds, gs) asm volatile("cp.async.ca.shared.global [%0], [%1], 16;" :: "r"(ds), "l"(gs))
#define CPCOMMIT()   asm volatile("cp.async.commit_group;")
#define CPWAIT1()    asm volatile("cp.async.wait_group 1;" ::: "memory")
#define CPWAIT0()    asm volatile("cp.async.wait_group 0;" ::: "memory")

// ---------------------------------------------------------------------------
// Kernel 1: embedding -> h0 (transposed layout)
// ---------------------------------------------------------------------------
__global__ void embed_kernel(const float* __restrict__ z_t,
                             const float* __restrict__ z_g,
                             const float* __restrict__ w_emb) {
    int row = blockIdx.x;
    int u   = threadIdx.x;
    __shared__ float zs[128];
    if (u < 64)        zs[u] = z_t[row * 64 + u];
    else if (u < 128)  zs[u] = z_g[(row >> 4) * 64 + (u & 63)];
    __syncthreads();
    const float* wr = w_emb + u * 128;
    float acc = 0.f;
#pragma unroll 16
    for (int k = 0; k < 128; ++k) acc = fmaf(zs[k], wr[k], acc);
    g_hT[0][u][row] = acc;
}

// ---------------------------------------------------------------------------
// Kernel 2: PERSISTENT GRU — all 128 steps in one launch.
// Grid: 128 CTAs (32 unit-blocks x 4 row-blocks), 256 threads.
// CTA tile: 8 units x 128 rows. Thread tile: 2 units x 2 rows (f32x2).
// W slice (8 units x 3 gates x 256) lives pre-splatted in smem for ALL steps.
// h tiles stream via cp.async, double-buffered 64-k chunks.
// Grid sync: monotonic global counter (all 128 CTAs co-resident on 148 SMs).
//
// smem: hbuf 2x[64][128] = 16384 f | wsA [8][257] float4 (r,r,z,z) = 8224 f |
//       wsB [8][257] float2 (n,n) = 4112 f  -> 28720 floats = 114880 B
// ---------------------------------------------------------------------------
#define GRU_SMEM_FLOATS (16384 + 8224 + 4112)
#define GRU_SMEM_BYTES  (GRU_SMEM_FLOATS * 4)

__device__ __forceinline__ float gate1(float gr, float gz, float gn, float h,
                                       float bir, float biz, float bin) {
    float r = 1.f / (1.f + expf(-(bir + gr)));
    float z = 1.f / (1.f + expf(-(biz + gz)));
    float n = tanhf(bin + r * gn);
    return (1.f - z) * n + z * h;
}

__global__ __launch_bounds__(256) void gru_persist_kernel(
        const float* __restrict__ w_hh,
        const float* __restrict__ b_ih,
        const float* __restrict__ b_hh) {
    extern __shared__ float sm[];
    float* wsA = sm + 16384;                   // [8][257][4] floats
    float* wsB = sm + 16384 + 8224;            // [8][257][2] floats

    const int tid = threadIdx.x;
    const int bx  = blockIdx.x;
    const int u0  = (bx >> 2) * 8;             // unit block (32 blocks)
    const int r0  = (bx & 3) * 128;            // row block (4 blocks)

    // ---- load + splat W slice ONCE ----
#pragma unroll
    for (int i = tid; i < 8 * 256; i += 256) {
        int uu = i >> 8, k = i & 255;
        float r = w_hh[(0 * EMB + u0 + uu) * EMB + k];
        float z = w_hh[(1 * EMB + u0 + uu) * EMB + k];
        float n = w_hh[(2 * EMB + u0 + uu) * EMB + k];
        *(float4*)&wsA[(uu * 257 + k) * 4] = make_float4(r, r, z, z);
        *(float2*)&wsB[(uu * 257 + k) * 2] = make_float2(n, n);
    }

    const int ux2 = tid & 3;                   // unit pair 0..3
    const int rg  = tid >> 2;                  // row pair 0..63
    const int uu0 = ux2 * 2, uu1 = uu0 + 1;
    const int j0  = u0 + uu0, j1 = u0 + uu1;

    // per-thread constants (biases), packed where useful
    const ull c_r0 = pack2(b_hh[j0], b_hh[j0]);
    const ull c_z0 = pack2(b_hh[EMB + j0], b_hh[EMB + j0]);
    const ull c_n0 = pack2(b_hh[2 * EMB + j0], b_hh[2 * EMB + j0]);
    const ull c_r1 = pack2(b_hh[j1], b_hh[j1]);
    const ull c_z1 = pack2(b_hh[EMB + j1], b_hh[EMB + j1]);
    const ull c_n1 = pack2(b_hh[2 * EMB + j1], b_hh[2 * EMB + j1]);
    const float bir0 = b_ih[j0], biz0 = b_ih[EMB + j0], bin0 = b_ih[2 * EMB + j0];
    const float bir1 = b_ih[j1], biz1 = b_ih[EMB + j1], bin1 = b_ih[2 * EMB + j1];

    const unsigned sbase = smaddr(sm);
    const ulonglong2* __restrict__ waP = (const ulonglong2*)wsA;  // [uu*257+k]
    const ull*        __restrict__ wbP = (const ull*)wsB;         // [uu*257+k]

    __syncthreads();

    for (int t = 1; t <= TSTEPS; ++t) {
        const float* hp = &g_hT[t - 1][0][0];

        // prologue: issue chunk 0 into buffer 0
#pragma unroll
        for (int it = 0; it < 8; ++it) {
            int lin = tid + it * 256;
            int kk = lin >> 5, c4 = lin & 31;
            CP16(sbase + kk * 512 + c4 * 16,
                 hp + (size_t)kk * BW + r0 + c4 * 4);
        }
        CPCOMMIT();

        ull ar0 = c_r0, az0 = c_z0, an0 = c_n0;
        ull ar1 = c_r1, az1 = c_z1, an1 = c_n1;

        for (int c = 0; c < 4; ++c) {
            if (c < 3) {
                unsigned dbase = sbase + (unsigned)(((c + 1) & 1) * 32768);
#pragma unroll
                for (int it = 0; it < 8; ++it) {
                    int lin = tid + it * 256;
                    int kk = lin >> 5, c4 = lin & 31;
                    CP16(dbase + kk * 512 + c4 * 16,
                         hp + (size_t)((c + 1) * 64 + kk) * BW + r0 + c4 * 4);
                }
                CPCOMMIT();
                CPWAIT1();
            } else {
                CPWAIT0();
            }
            __syncthreads();

            const ull* hb = (const ull*)(sm + (c & 1) * 8192);  // [kk][64 ull]
            const int kbase = c * 64;
#pragma unroll 4
            for (int kk = 0; kk < 64; ++kk) {
                ull h2 = hb[kk * 64 + rg];
                int k  = kbase + kk;
                ulonglong2 wa0 = waP[uu0 * 257 + k];   // (r,r | z,z)
                ulonglong2 wa1 = waP[uu1 * 257 + k];
                ull wn0 = wbP[uu0 * 257 + k];          // (n,n)
                ull wn1 = wbP[uu1 * 257 + k];
                ffma2(ar0, h2, wa0.x);
                ffma2(az0, h2, wa0.y);
                ffma2(an0, h2, wn0);
                ffma2(ar1, h2, wa1.x);
                ffma2(az1, h2, wa1.y);
                ffma2(an1, h2, wn1);
            }
            __syncthreads();   // protect buffer before next-next chunk load
        }

        // ---- gates + store ----
        {
            float2 gr0 = unpk(ar0), gz0 = unpk(az0), gn0 = unpk(an0);
            float2 gr1 = unpk(ar1), gz1 = unpk(az1), gn1 = unpk(an1);
            float2 h0v = *(const float2*)(hp + (size_t)j0 * BW + r0 + rg * 2);
            float2 h1v = *(const float2*)(hp + (size_t)j1 * BW + r0 + rg * 2);
            float2 o0, o1;
            o0.x = gate1(gr0.x, gz0.x, gn0.x, h0v.x, bir0, biz0, bin0);
            o0.y = gate1(gr0.y, gz0.y, gn0.y, h0v.y, bir0, biz0, bin0);
            o1.x = gate1(gr1.x, gz1.x, gn1.x, h1v.x, bir1, biz1, bin1);
            o1.y = gate1(gr1.y, gz1.y, gn1.y, h1v.y, bir1, biz1, bin1);
            *(float2*)(&g_hT[t][j0][r0 + rg * 2]) = o0;
            *(float2*)(&g_hT[t][j1][r0 + rg * 2]) = o1;
        }

        // ---- grid barrier (monotonic counter; no reset, no phase bug) ----
        __syncthreads();
        if (tid == 0) {
            __threadfence();
            atomicAdd(&g_bar, 1u);
            unsigned target = 128u * (unsigned)t;
            while (*(volatile unsigned*)&g_bar < target) { }
            __threadfence();
        }
        __syncthreads();
    }
}

// ---------------------------------------------------------------------------
// Kernel 3: fp32 GEMM with FFMA2 inner loop.  C = act(A @ Wt^T + bias)
// ---------------------------------------------------------------------------
template <int BN, int TN, bool ATRANS, bool DOELU, bool SCATTER>
__global__ __launch_bounds__(256) void gemm_kernel(
        const float* __restrict__ A,
        const float* __restrict__ Wt,
        const float* __restrict__ bias,
        float* __restrict__ C,
        int K, int N) {
    constexpr int BM = 128, BK = 16;
    constexpr int WS  = BN + 4;
    constexpr int WS4 = WS / 4;
    constexpr int TN2 = TN / 2;
    __shared__ float4 As4[BK * BM / 4];
    __shared__ float4 Ws4s[BK * WS4];
    float* As = (float*)As4;
    float* Ws = (float*)Ws4s;

    const int tid = threadIdx.x;
    const int tx  = tid & 15;
    const int ty  = tid >> 4;
    const int bn  = blockIdx.x * BN;
    const int bm  = blockIdx.y * BM;

    const float* Abase = A;
    if (ATRANS) Abase = A + (size_t)(bm >> 9) * (EMB * BW) + (bm & 511);

    // bias-initialized packed accumulators
    ull acc2[8][TN2];
    {
        ull binit[TN2];
#pragma unroll
        for (int j = 0; j < TN2; ++j)
            binit[j] = pack2(bias[bn + tx * TN + 2 * j],
                             bias[bn + tx * TN + 2 * j + 1]);
#pragma unroll
        for (int i = 0; i < 8; ++i)
#pragma unroll
            for (int j = 0; j < TN2; ++j) acc2[i][j] = binit[j];
    }

    for (int k0 = 0; k0 < K; k0 += BK) {
        if (ATRANS) {
#pragma unroll
            for (int i = tid; i < 512; i += 256) {
                int k = i >> 5, r4 = i & 31;
                As4[k * 32 + r4] =
                    *(const float4*)(Abase + (size_t)(k0 + k) * BW + r4 * 4);
            }
        } else {
#pragma unroll
            for (int i = tid; i < 512; i += 256) {
                int row = i >> 2, kq = i & 3;
                float4 v = *(const float4*)(A + (size_t)(bm + row) * K + k0 + kq * 4);
                As[(kq * 4 + 0) * BM + row] = v.x;
                As[(kq * 4 + 1) * BM + row] = v.y;
                As[(kq * 4 + 2) * BM + row] = v.z;
                As[(kq * 4 + 3) * BM + row] = v.w;
            }
        }
#pragma unroll
        for (int i = tid; i < BN * 4; i += 256) {
            int n = i >> 2, kq = i & 3;
            float4 v = *(const float4*)(Wt + (size_t)(bn + n) * K + k0 + kq * 4);
            Ws[(kq * 4 + 0) * WS + n] = v.x;
            Ws[(kq * 4 + 1) * WS + n] = v.y;
            Ws[(kq * 4 + 2) * WS + n] = v.z;
            Ws[(kq * 4 + 3) * WS + n] = v.w;
        }
        __syncthreads();

#pragma unroll
        for (int k = 0; k < BK; ++k) {
            float4 a0 = As4[k * 32 + ty * 2];
            float4 a1 = As4[k * 32 + ty * 2 + 1];
            float av[8] = {a0.x, a0.y, a0.z, a0.w, a1.x, a1.y, a1.z, a1.w};
            const ull* bp = (const ull*)(Ws + k * WS + tx * TN);
            ull bv[TN2];
#pragma unroll
            for (int j = 0; j < TN2; ++j) bv[j] = bp[j];
#pragma unroll
            for (int i = 0; i < 8; ++i) {
                ull as2 = pack2(av[i], av[i]);
#pragma unroll
                for (int j = 0; j < TN2; ++j) ffma2(acc2[i][j], as2, bv[j]);
            }
        }
        __syncthreads();
    }

    // epilogue
#pragma unroll
    for (int i = 0; i < 8; ++i) {
        int m = bm + ty * 8 + i;
        float o[TN];
#pragma unroll
        for (int j = 0; j < TN2; ++j) {
            float2 v = unpk(acc2[i][j]);
            if (DOELU) {
                v.x = (v.x > 0.f) ? v.x : expm1f(v.x);
                v.y = (v.y > 0.f) ? v.y : expm1f(v.y);
            }
            o[2 * j] = v.x; o[2 * j + 1] = v.y;
        }
        float* dst;
        if (SCATTER) {
            int rowbw = m & 511, tt = m >> 9;
            dst = C + ((size_t)(rowbw * TSTEPS + tt)) * OUTD + tx * TN;
        } else {
            dst = C + (size_t)m * N + bn + tx * TN;
        }
#pragma unroll
        for (int j4 = 0; j4 < TN; j4 += 4)
            *(float4*)(dst + j4) = make_float4(o[j4], o[j4 + 1], o[j4 + 2], o[j4 + 3]);
    }
}

// ---------------------------------------------------------------------------
// Host launcher
// ---------------------------------------------------------------------------
extern "C" void kernel_launch(void* const* d_in, const int* in_sizes, int n_in,
                              void* d_out, int out_size) {
    (void)in_sizes; (void)n_in; (void)out_size;
    const float* z_t   = (const float*)d_in[0];
    const float* z_g   = (const float*)d_in[1];
    const float* w_emb = (const float*)d_in[2];
    const float* w_hh  = (const float*)d_in[3];
    const float* b_ih  = (const float*)d_in[4];
    const float* b_hh  = (const float*)d_in[5];
    const float* w1    = (const float*)d_in[6];
    const float* b1    = (const float*)d_in[7];
    const float* w2    = (const float*)d_in[8];
    const float* b2    = (const float*)d_in[9];
    const float* w3    = (const float*)d_in[10];
    const float* b3    = (const float*)d_in[11];
    const float* muw   = (const float*)d_in[12];
    const float* mub   = (const float*)d_in[13];
    float* out = (float*)d_out;

    float *hT, *act1, *act2;
    unsigned* barp;
    cudaGetSymbolAddress((void**)&hT,   g_hT);
    cudaGetSymbolAddress((void**)&act1, g_act1);
    cudaGetSymbolAddress((void**)&act2, g_act2);
    cudaGetSymbolAddress((void**)&barp, g_bar);

    cudaFuncSetAttribute(gru_persist_kernel,
                         cudaFuncAttributeMaxDynamicSharedMemorySize,
                         GRU_SMEM_BYTES);

    // reset grid-barrier counter (memset node: graph-capturable)
    cudaMemsetAsync(barp, 0, sizeof(unsigned));

    // 1) embedding -> h0
    embed_kernel<<<512, 256>>>(z_t, z_g, w_emb);

    // 2) persistent GRU: all 128 steps in one launch
    gru_persist_kernel<<<128, 256, GRU_SMEM_BYTES>>>(w_hh, b_ih, b_hh);

    // 3) MLP
    const float* h_seq = hT + (size_t)EMB * BW;   // &g_hT[1][0][0]
    gemm_kernel<128, 8, true,  true,  false>
        <<<dim3(HID / 128, MTOT / 128), 256>>>(h_seq, w1, b1, act1, EMB, HID);
    gemm_kernel<128, 8, false, true,  false>
        <<<dim3(HID / 128, MTOT / 128), 256>>>(act1, w2, b2, act2, HID, HID);
    gemm_kernel<128, 8, false, true,  false>
        <<<dim3(HID / 128, MTOT / 128), 256>>>(act2, w3, b3, act1, HID, HID);

    // 4) mu head with scatter
    gemm_kernel<64, 4, false, false, true>
        <<<dim3(1, MTOT / 128), 256>>>(act1, muw, mub, out, HID, OUTD);
}

// round 9
// speedup vs baseline: 1.8970x; 1.3268x over previous
#include <cuda_runtime.h>
#include <cuda_bf16.h>
#include <math.h>
#include <stdint.h>

// Problem constants
#define BATCH   32
#define NW      16
#define BW      512
#define EMB     256
#define HID     512
#define OUTD    64
#define TSTEPS  128
#define MTOT    (BW * TSTEPS)

// ---------------------------------------------------------------------------
// Scratch (device globals)
// ---------------------------------------------------------------------------
__device__ float g_hT[(TSTEPS + 1)][EMB][BW];           // [t][unit][row] fp32
__device__ float g_act1[(size_t)MTOT * HID];            // L3 fp32 out (mu input)
__device__ unsigned int g_bar;                          // GRU grid barrier

// bf16 split activations (hi + lo ~= fp32)
__device__ __nv_bfloat16 g_a0hi[(size_t)MTOT * EMB];
__device__ __nv_bfloat16 g_a0lo[(size_t)MTOT * EMB];
__device__ __nv_bfloat16 g_b1hi[(size_t)MTOT * HID];
__device__ __nv_bfloat16 g_b1lo[(size_t)MTOT * HID];
__device__ __nv_bfloat16 g_b2hi[(size_t)MTOT * HID];
__device__ __nv_bfloat16 g_b2lo[(size_t)MTOT * HID];
// bf16 split weights
__device__ __nv_bfloat16 g_w1hi[HID * EMB], g_w1lo[HID * EMB];
__device__ __nv_bfloat16 g_w2hi[HID * HID], g_w2lo[HID * HID];
__device__ __nv_bfloat16 g_w3hi[HID * HID], g_w3lo[HID * HID];

// ---------------------------------------------------------------------------
// helpers
// ---------------------------------------------------------------------------
typedef unsigned long long ull;
__device__ __forceinline__ ull pack2(float x, float y) {
    ull r; asm("mov.b64 %0, {%1,%2};" : "=l"(r) : "f"(x), "f"(y)); return r;
}
__device__ __forceinline__ void ffma2(ull& d, ull a, ull b) {
    asm("fma.rn.f32x2 %0, %1, %2, %0;" : "+l"(d) : "l"(a), "l"(b));
}
__device__ __forceinline__ float2 unpk(ull v) {
    float2 f; asm("mov.b64 {%0,%1}, %2;" : "=f"(f.x), "=f"(f.y) : "l"(v)); return f;
}
__device__ __forceinline__ unsigned smaddr(const void* p) {
    unsigned r;
    asm("{.reg .u64 t; cvta.to.shared.u64 t, %1; cvt.u32.u64 %0, t;}"
        : "=r"(r) : "l"(p));
    return r;
}
#define CP16(ds, gs) asm volatile("cp.async.ca.shared.global [%0], [%1], 16;" :: "r"(ds), "l"(gs))
#define CPCOMMIT()   asm volatile("cp.async.commit_group;")
#define CPWAIT1()    asm volatile("cp.async.wait_group 1;" ::: "memory")
#define CPWAIT0()    asm volatile("cp.async.wait_group 0;" ::: "memory")

// ldmatrix x4 (b16) — lane i supplies the address of 8x8-tile row for its segment
#define LDSM4(r, addr)                                                       \
    asm volatile("ldmatrix.sync.aligned.m8n8.x4.shared.b16 {%0,%1,%2,%3}, [%4];" \
        : "=r"((r)[0]), "=r"((r)[1]), "=r"((r)[2]), "=r"((r)[3]) : "r"(addr))

// mma m16n8k16 row.col bf16 -> f32 accum (in-place)
#define MMA16816(d, a, b0, b1)                                               \
    asm volatile("mma.sync.aligned.m16n8k16.row.col.f32.bf16.bf16.f32 "      \
        "{%0,%1,%2,%3}, {%4,%5,%6,%7}, {%8,%9}, {%0,%1,%2,%3};"              \
        : "+f"((d)[0]), "+f"((d)[1]), "+f"((d)[2]), "+f"((d)[3])             \
        : "r"((a)[0]), "r"((a)[1]), "r"((a)[2]), "r"((a)[3]),                \
          "r"(b0), "r"(b1))

// ---------------------------------------------------------------------------
// Kernel 1: embedding -> h0 (transposed layout)
// ---------------------------------------------------------------------------
__global__ void embed_kernel(const float* __restrict__ z_t,
                             const float* __restrict__ z_g,
                             const float* __restrict__ w_emb) {
    int row = blockIdx.x;
    int u   = threadIdx.x;
    __shared__ float zs[128];
    if (u < 64)        zs[u] = z_t[row * 64 + u];
    else if (u < 128)  zs[u] = z_g[(row >> 4) * 64 + (u & 63)];
    __syncthreads();
    const float* wr = w_emb + u * 128;
    float acc = 0.f;
#pragma unroll 16
    for (int k = 0; k < 128; ++k) acc = fmaf(zs[k], wr[k], acc);
    g_hT[0][u][row] = acc;
}

// ---------------------------------------------------------------------------
// Kernel W: split fp32 weights -> bf16 hi/lo
// ---------------------------------------------------------------------------
__global__ void wsplit_kernel(const float* __restrict__ w,
                              __nv_bfloat16* __restrict__ hi,
                              __nv_bfloat16* __restrict__ lo, int n) {
    int i = blockIdx.x * 256 + threadIdx.x;
    if (i < n) {
        float v = w[i];
        __nv_bfloat16 h = __float2bfloat16(v);
        hi[i] = h;
        lo[i] = __float2bfloat16(v - __bfloat162float(h));
    }
}

// ---------------------------------------------------------------------------
// Kernel 2: persistent GRU (128 steps, one launch). Proven structure (R5).
// Gate math switched to fast intrinsics (__expf / __fdividef, err ~2^-22).
// Also emits bf16 hi/lo split of h into g_a0{hi,lo} [m][k], m=(t-1)*512+row.
// ---------------------------------------------------------------------------
#define GRU_SMEM_FLOATS (16384 + 8224 + 4112)
#define GRU_SMEM_BYTES  (GRU_SMEM_FLOATS * 4)

__device__ __forceinline__ float sigm_fast(float x) {
    return __fdividef(1.f, 1.f + __expf(-x));
}
__device__ __forceinline__ float tanh_fast(float x) {
    float t = __expf(2.f * x);
    return 1.f - __fdividef(2.f, t + 1.f);
}
__device__ __forceinline__ float gate1(float gr, float gz, float gn, float h,
                                       float bir, float biz, float bin) {
    float r = sigm_fast(bir + gr);
    float z = sigm_fast(biz + gz);
    float n = tanh_fast(bin + r * gn);
    return (1.f - z) * n + z * h;
}

__global__ __launch_bounds__(256) void gru_persist_kernel(
        const float* __restrict__ w_hh,
        const float* __restrict__ b_ih,
        const float* __restrict__ b_hh) {
    extern __shared__ float sm[];
    float* wsA = sm + 16384;                   // [8][257][4]
    float* wsB = sm + 16384 + 8224;            // [8][257][2]

    const int tid = threadIdx.x;
    const int bx  = blockIdx.x;
    const int u0  = (bx >> 2) * 8;
    const int r0  = (bx & 3) * 128;

#pragma unroll
    for (int i = tid; i < 8 * 256; i += 256) {
        int uu = i >> 8, k = i & 255;
        float r = w_hh[(0 * EMB + u0 + uu) * EMB + k];
        float z = w_hh[(1 * EMB + u0 + uu) * EMB + k];
        float n = w_hh[(2 * EMB + u0 + uu) * EMB + k];
        *(float4*)&wsA[(uu * 257 + k) * 4] = make_float4(r, r, z, z);
        *(float2*)&wsB[(uu * 257 + k) * 2] = make_float2(n, n);
    }

    const int ux2 = tid & 3;
    const int rg  = tid >> 2;
    const int uu0 = ux2 * 2, uu1 = uu0 + 1;
    const int j0  = u0 + uu0, j1 = u0 + uu1;

    const ull c_r0 = pack2(b_hh[j0], b_hh[j0]);
    const ull c_z0 = pack2(b_hh[EMB + j0], b_hh[EMB + j0]);
    const ull c_n0 = pack2(b_hh[2 * EMB + j0], b_hh[2 * EMB + j0]);
    const ull c_r1 = pack2(b_hh[j1], b_hh[j1]);
    const ull c_z1 = pack2(b_hh[EMB + j1], b_hh[EMB + j1]);
    const ull c_n1 = pack2(b_hh[2 * EMB + j1], b_hh[2 * EMB + j1]);
    const float bir0 = b_ih[j0], biz0 = b_ih[EMB + j0], bin0 = b_ih[2 * EMB + j0];
    const float bir1 = b_ih[j1], biz1 = b_ih[EMB + j1], bin1 = b_ih[2 * EMB + j1];

    const unsigned sbase = smaddr(sm);
    const ulonglong2* __restrict__ waP = (const ulonglong2*)wsA;
    const ull*        __restrict__ wbP = (const ull*)wsB;

    __syncthreads();

    for (int t = 1; t <= TSTEPS; ++t) {
        const float* hp = &g_hT[t - 1][0][0];

#pragma unroll
        for (int it = 0; it < 8; ++it) {
            int lin = tid + it * 256;
            int kk = lin >> 5, c4 = lin & 31;
            CP16(sbase + kk * 512 + c4 * 16, hp + (size_t)kk * BW + r0 + c4 * 4);
        }
        CPCOMMIT();

        ull ar0 = c_r0, az0 = c_z0, an0 = c_n0;
        ull ar1 = c_r1, az1 = c_z1, an1 = c_n1;

        for (int c = 0; c < 4; ++c) {
            if (c < 3) {
                unsigned dbase = sbase + (unsigned)(((c + 1) & 1) * 32768);
#pragma unroll
                for (int it = 0; it < 8; ++it) {
                    int lin = tid + it * 256;
                    int kk = lin >> 5, c4 = lin & 31;
                    CP16(dbase + kk * 512 + c4 * 16,
                         hp + (size_t)((c + 1) * 64 + kk) * BW + r0 + c4 * 4);
                }
                CPCOMMIT();
                CPWAIT1();
            } else {
                CPWAIT0();
            }
            __syncthreads();

            const ull* hb = (const ull*)(sm + (c & 1) * 8192);
            const int kbase = c * 64;
#pragma unroll 4
            for (int kk = 0; kk < 64; ++kk) {
                ull h2 = hb[kk * 64 + rg];
                int k  = kbase + kk;
                ulonglong2 wa0 = waP[uu0 * 257 + k];
                ulonglong2 wa1 = waP[uu1 * 257 + k];
                ull wn0 = wbP[uu0 * 257 + k];
                ull wn1 = wbP[uu1 * 257 + k];
                ffma2(ar0, h2, wa0.x);
                ffma2(az0, h2, wa0.y);
                ffma2(an0, h2, wn0);
                ffma2(ar1, h2, wa1.x);
                ffma2(az1, h2, wa1.y);
                ffma2(an1, h2, wn1);
            }
            __syncthreads();
        }

        {
            float2 gr0 = unpk(ar0), gz0 = unpk(az0), gn0 = unpk(an0);
            float2 gr1 = unpk(ar1), gz1 = unpk(az1), gn1 = unpk(an1);
            float2 h0v = *(const float2*)(hp + (size_t)j0 * BW + r0 + rg * 2);
            float2 h1v = *(const float2*)(hp + (size_t)j1 * BW + r0 + rg * 2);
            float2 o0, o1;
            o0.x = gate1(gr0.x, gz0.x, gn0.x, h0v.x, bir0, biz0, bin0);
            o0.y = gate1(gr0.y, gz0.y, gn0.y, h0v.y, bir0, biz0, bin0);
            o1.x = gate1(gr1.x, gz1.x, gn1.x, h1v.x, bir1, biz1, bin1);
            o1.y = gate1(gr1.y, gz1.y, gn1.y, h1v.y, bir1, biz1, bin1);
            *(float2*)(&g_hT[t][j0][r0 + rg * 2]) = o0;
            *(float2*)(&g_hT[t][j1][r0 + rg * 2]) = o1;

            size_t m0 = (size_t)(t - 1) * BW + r0 + rg * 2;
            __nv_bfloat162 h2a, l2a, h2b, l2b;
            h2a.x = __float2bfloat16(o0.x);
            h2a.y = __float2bfloat16(o1.x);
            l2a.x = __float2bfloat16(o0.x - __bfloat162float(h2a.x));
            l2a.y = __float2bfloat16(o1.x - __bfloat162float(h2a.y));
            h2b.x = __float2bfloat16(o0.y);
            h2b.y = __float2bfloat16(o1.y);
            l2b.x = __float2bfloat16(o0.y - __bfloat162float(h2b.x));
            l2b.y = __float2bfloat16(o1.y - __bfloat162float(h2b.y));
            *(__nv_bfloat162*)&g_a0hi[m0 * EMB + j0]       = h2a;
            *(__nv_bfloat162*)&g_a0lo[m0 * EMB + j0]       = l2a;
            *(__nv_bfloat162*)&g_a0hi[(m0 + 1) * EMB + j0] = h2b;
            *(__nv_bfloat162*)&g_a0lo[(m0 + 1) * EMB + j0] = l2b;
        }

        __syncthreads();
        if (tid == 0) {
            __threadfence();
            atomicAdd(&g_bar, 1u);
            unsigned target = 128u * (unsigned)t;
            while (*(volatile unsigned*)&g_bar < target) { }
            __threadfence();
        }
        __syncthreads();
    }
}

// ---------------------------------------------------------------------------
// Kernel 3: HMMA (mma.sync m16n8k16 bf16) split GEMM. C = ELU(A@W^T + bias)
//   acc += Ahi*Whi + Ahi*Wlo + Alo*Whi  (fp32 accumulators; lo*lo dropped)
// CTA 128x128, BK=64, 8 warps (32m x 64n each), double-buffered cp.async.
// smem tiles: [128 rows][64 bf16] = 16KB each (Ahi,Alo,Whi,Wlo), row=128B,
// 16B-chunk swizzle: chunk ^= (row & 7)  -> ldmatrix conflict-free.
// ---------------------------------------------------------------------------
#define HG_SMEM_BYTES (512 + 2 * 4 * 16384)    // bias + 2 stages x 4 tiles

template <int K, bool OUTBF16>
__global__ __launch_bounds__(256) void hmma_gemm_kernel(
        const __nv_bfloat16* __restrict__ Ahi, const __nv_bfloat16* __restrict__ Alo,
        const __nv_bfloat16* __restrict__ Whi, const __nv_bfloat16* __restrict__ Wlo,
        const float* __restrict__ bias,
        __nv_bfloat16* __restrict__ Chi, __nv_bfloat16* __restrict__ Clo,
        float* __restrict__ Cf) {
    constexpr int NC = K / 64;
    extern __shared__ char smem[];
    float* sbias = (float*)smem;
    const unsigned stile = smaddr(smem) + 512;

    const int tid  = threadIdx.x;
    const int wid  = tid >> 5, lane = tid & 31;
    const int wm   = wid & 3;            // warp m block (x32)
    const int wn   = wid >> 2;           // warp n block (x64)
    const int bn   = blockIdx.x * 128;
    const int bm   = blockIdx.y * 128;

    if (tid < 128) sbias[tid] = bias[bn + tid];

    auto load_chunk = [&](int c) {
        unsigned sb = stile + (unsigned)((c & 1) * 65536);
        int k0 = c * 64;
#pragma unroll
        for (int it = 0; it < 4; ++it) {
            int i = tid + it * 256;
            int row = i >> 3, cc = i & 7;
            unsigned sw = (unsigned)(row * 128 + ((cc ^ (row & 7)) << 4));
            size_t aoff = (size_t)(bm + row) * K + k0 + cc * 8;
            size_t woff = (size_t)(bn + row) * K + k0 + cc * 8;
            CP16(sb + sw,         Ahi + aoff);
            CP16(sb + 16384 + sw, Alo + aoff);
            CP16(sb + 32768 + sw, Whi + woff);
            CP16(sb + 49152 + sw, Wlo + woff);
        }
        CPCOMMIT();
    };

    float acc[2][8][4];
#pragma unroll
    for (int i = 0; i < 2; ++i)
#pragma unroll
        for (int j = 0; j < 8; ++j)
#pragma unroll
            for (int q = 0; q < 4; ++q) acc[i][j][q] = 0.f;

    // ldmatrix lane mapping: seg 0..3 -> (m8 half, kc half)
    const int seg  = lane >> 3, lrow = lane & 7;
    const int rA   = wm * 32 + (seg & 1) * 8 + lrow;   // + ma*16
    const int rB   = wn * 64 + (seg & 1) * 8 + lrow;   // + ng*16
    const int csel = seg >> 1;

    load_chunk(0);
    for (int c = 0; c < NC; ++c) {
        if (c + 1 < NC) { load_chunk(c + 1); CPWAIT1(); }
        else            { CPWAIT0(); }
        __syncthreads();
        unsigned sb = stile + (unsigned)((c & 1) * 65536);

#pragma unroll
        for (int s = 0; s < 4; ++s) {       // 4 x k16 within the 64-k chunk
            int kc = s * 2 + csel;
            unsigned ah[2][4], al[2][4];
#pragma unroll
            for (int ma = 0; ma < 2; ++ma) {
                int row = rA + ma * 16;
                unsigned addr = sb + (unsigned)(row * 128 + ((kc ^ (row & 7)) << 4));
                LDSM4(ah[ma], addr);
                LDSM4(al[ma], addr + 16384);
            }
            unsigned bh[4][4], bl[4][4];
#pragma unroll
            for (int ng = 0; ng < 4; ++ng) {
                int row = rB + ng * 16;
                unsigned addr = sb + 32768u +
                                (unsigned)(row * 128 + ((kc ^ (row & 7)) << 4));
                LDSM4(bh[ng], addr);
                LDSM4(bl[ng], addr + 16384);
            }
#pragma unroll
            for (int ma = 0; ma < 2; ++ma)
#pragma unroll
                for (int na = 0; na < 8; ++na) {
                    int ng = na >> 1, hf = na & 1;
                    MMA16816(acc[ma][na], ah[ma], bh[ng][hf], bh[ng][2 + hf]);
                    MMA16816(acc[ma][na], ah[ma], bl[ng][hf], bl[ng][2 + hf]);
                    MMA16816(acc[ma][na], al[ma], bh[ng][hf], bh[ng][2 + hf]);
                }
        }
        __syncthreads();
    }

    // epilogue: c0,c1 -> row grp, cols q*2,q*2+1 ; c2,c3 -> row grp+8
    const int grp = lane >> 2, qid = lane & 3;
#pragma unroll
    for (int ma = 0; ma < 2; ++ma) {
#pragma unroll
        for (int na = 0; na < 8; ++na) {
            int col = wn * 64 + na * 8 + qid * 2;          // within 128-tile
            float b0v = sbias[col], b1v = sbias[col + 1];
#pragma unroll
            for (int hf = 0; hf < 2; ++hf) {
                int m = bm + wm * 32 + ma * 16 + grp + hf * 8;
                float v0 = acc[ma][na][hf * 2 + 0] + b0v;
                float v1 = acc[ma][na][hf * 2 + 1] + b1v;
                v0 = (v0 > 0.f) ? v0 : expm1f(v0);
                v1 = (v1 > 0.f) ? v1 : expm1f(v1);
                if (OUTBF16) {
                    __nv_bfloat162 h2, l2;
                    h2.x = __float2bfloat16(v0);
                    h2.y = __float2bfloat16(v1);
                    l2.x = __float2bfloat16(v0 - __bfloat162float(h2.x));
                    l2.y = __float2bfloat16(v1 - __bfloat162float(h2.y));
                    *(__nv_bfloat162*)(Chi + (size_t)m * HID + bn + col) = h2;
                    *(__nv_bfloat162*)(Clo + (size_t)m * HID + bn + col) = l2;
                } else {
                    *(float2*)(Cf + (size_t)m * HID + bn + col) =
                        make_float2(v0, v1);
                }
            }
        }
    }
}

// ---------------------------------------------------------------------------
// Kernel 4: scalar FFMA2 mu head (N=64, K=512), fp32 in, scatter out.
// ---------------------------------------------------------------------------
__global__ __launch_bounds__(256) void mu_kernel(
        const float* __restrict__ A,
        const float* __restrict__ Wt,
        const float* __restrict__ bias,
        float* __restrict__ C) {
    constexpr int BM = 128, BK = 16, BN = 64, TN = 4, TN2 = 2;
    constexpr int WS = BN + 4, WS4 = WS / 4;
    constexpr int K = HID;
    __shared__ float4 As4[BK * BM / 4];
    __shared__ float4 Ws4s[BK * WS4];
    float* As = (float*)As4;
    float* Ws = (float*)Ws4s;

    const int tid = threadIdx.x;
    const int tx  = tid & 15;
    const int ty  = tid >> 4;
    const int bm  = blockIdx.y * BM;

    ull acc2[8][TN2];
    {
        ull binit[TN2];
#pragma unroll
        for (int j = 0; j < TN2; ++j)
            binit[j] = pack2(bias[tx * TN + 2 * j], bias[tx * TN + 2 * j + 1]);
#pragma unroll
        for (int i = 0; i < 8; ++i)
#pragma unroll
            for (int j = 0; j < TN2; ++j) acc2[i][j] = binit[j];
    }

    for (int k0 = 0; k0 < K; k0 += BK) {
#pragma unroll
        for (int i = tid; i < 512; i += 256) {
            int row = i >> 2, kq = i & 3;
            float4 v = *(const float4*)(A + (size_t)(bm + row) * K + k0 + kq * 4);
            As[(kq * 4 + 0) * BM + row] = v.x;
            As[(kq * 4 + 1) * BM + row] = v.y;
            As[(kq * 4 + 2) * BM + row] = v.z;
            As[(kq * 4 + 3) * BM + row] = v.w;
        }
#pragma unroll
        for (int i = tid; i < BN * 4; i += 256) {
            int n = i >> 2, kq = i & 3;
            float4 v = *(const float4*)(Wt + (size_t)n * K + k0 + kq * 4);
            Ws[(kq * 4 + 0) * WS + n] = v.x;
            Ws[(kq * 4 + 1) * WS + n] = v.y;
            Ws[(kq * 4 + 2) * WS + n] = v.z;
            Ws[(kq * 4 + 3) * WS + n] = v.w;
        }
        __syncthreads();

#pragma unroll
        for (int k = 0; k < BK; ++k) {
            float4 a0 = As4[k * 32 + ty * 2];
            float4 a1 = As4[k * 32 + ty * 2 + 1];
            float av[8] = {a0.x, a0.y, a0.z, a0.w, a1.x, a1.y, a1.z, a1.w};
            const ull* bp = (const ull*)(Ws + k * WS + tx * TN);
            ull bv[TN2];
#pragma unroll
            for (int j = 0; j < TN2; ++j) bv[j] = bp[j];
#pragma unroll
            for (int i = 0; i < 8; ++i) {
                ull as2 = pack2(av[i], av[i]);
#pragma unroll
                for (int j = 0; j < TN2; ++j) ffma2(acc2[i][j], as2, bv[j]);
            }
        }
        __syncthreads();
    }

#pragma unroll
    for (int i = 0; i < 8; ++i) {
        int m = bm + ty * 8 + i;
        float o[TN];
#pragma unroll
        for (int j = 0; j < TN2; ++j) {
            float2 v = unpk(acc2[i][j]);
            o[2 * j] = v.x; o[2 * j + 1] = v.y;
        }
        int rowbw = m & 511, tt = m >> 9;
        float* dst = C + ((size_t)(rowbw * TSTEPS + tt)) * OUTD + tx * TN;
        *(float4*)dst = make_float4(o[0], o[1], o[2], o[3]);
    }
}

// ---------------------------------------------------------------------------
// Host launcher (graph-capturable)
// ---------------------------------------------------------------------------
extern "C" void kernel_launch(void* const* d_in, const int* in_sizes, int n_in,
                              void* d_out, int out_size) {
    (void)in_sizes; (void)n_in; (void)out_size;
    const float* z_t   = (const float*)d_in[0];
    const float* z_g   = (const float*)d_in[1];
    const float* w_emb = (const float*)d_in[2];
    const float* w_hh  = (const float*)d_in[3];
    const float* b_ih  = (const float*)d_in[4];
    const float* b_hh  = (const float*)d_in[5];
    const float* w1    = (const float*)d_in[6];
    const float* b1    = (const float*)d_in[7];
    const float* w2    = (const float*)d_in[8];
    const float* b2    = (const float*)d_in[9];
    const float* w3    = (const float*)d_in[10];
    const float* b3    = (const float*)d_in[11];
    const float* muw   = (const float*)d_in[12];
    const float* mub   = (const float*)d_in[13];
    float* out = (float*)d_out;

    float* act1;
    unsigned* barp;
    __nv_bfloat16 *a0hi, *a0lo, *b1hi, *b1lo, *b2hi, *b2lo;
    __nv_bfloat16 *w1hi, *w1lo, *w2hi, *w2lo, *w3hi, *w3lo;
    cudaGetSymbolAddress((void**)&act1, g_act1);
    cudaGetSymbolAddress((void**)&barp, g_bar);
    cudaGetSymbolAddress((void**)&a0hi, g_a0hi);
    cudaGetSymbolAddress((void**)&a0lo, g_a0lo);
    cudaGetSymbolAddress((void**)&b1hi, g_b1hi);
    cudaGetSymbolAddress((void**)&b1lo, g_b1lo);
    cudaGetSymbolAddress((void**)&b2hi, g_b2hi);
    cudaGetSymbolAddress((void**)&b2lo, g_b2lo);
    cudaGetSymbolAddress((void**)&w1hi, g_w1hi);
    cudaGetSymbolAddress((void**)&w1lo, g_w1lo);
    cudaGetSymbolAddress((void**)&w2hi, g_w2hi);
    cudaGetSymbolAddress((void**)&w2lo, g_w2lo);
    cudaGetSymbolAddress((void**)&w3hi, g_w3hi);
    cudaGetSymbolAddress((void**)&w3lo, g_w3lo);

    cudaFuncSetAttribute(gru_persist_kernel,
                         cudaFuncAttributeMaxDynamicSharedMemorySize, GRU_SMEM_BYTES);
    cudaFuncSetAttribute(hmma_gemm_kernel<EMB, true>,
                         cudaFuncAttributeMaxDynamicSharedMemorySize, HG_SMEM_BYTES);
    cudaFuncSetAttribute(hmma_gemm_kernel<HID, true>,
                         cudaFuncAttributeMaxDynamicSharedMemorySize, HG_SMEM_BYTES);
    cudaFuncSetAttribute(hmma_gemm_kernel<HID, false>,
                         cudaFuncAttributeMaxDynamicSharedMemorySize, HG_SMEM_BYTES);

    cudaMemsetAsync(barp, 0, sizeof(unsigned));

    // weight splits
    wsplit_kernel<<<(HID * EMB + 255) / 256, 256>>>(w1, w1hi, w1lo, HID * EMB);
    wsplit_kernel<<<(HID * HID + 255) / 256, 256>>>(w2, w2hi, w2lo, HID * HID);
    wsplit_kernel<<<(HID * HID + 255) / 256, 256>>>(w3, w3hi, w3lo, HID * HID);

    // 1) embedding -> h0
    embed_kernel<<<512, 256>>>(z_t, z_g, w_emb);

    // 2) persistent GRU (also writes bf16 split of h into g_a0)
    gru_persist_kernel<<<128, 256, GRU_SMEM_BYTES>>>(w_hh, b_ih, b_hh);

    // 3) MLP on tensor cores via mma.sync (bf16-split, fp32 accum)
    hmma_gemm_kernel<EMB, true><<<dim3(HID / 128, MTOT / 128), 256, HG_SMEM_BYTES>>>(
        a0hi, a0lo, w1hi, w1lo, b1, b1hi, b1lo, nullptr);
    hmma_gemm_kernel<HID, true><<<dim3(HID / 128, MTOT / 128), 256, HG_SMEM_BYTES>>>(
        b1hi, b1lo, w2hi, w2lo, b2, b2hi, b2lo, nullptr);
    hmma_gemm_kernel<HID, false><<<dim3(HID / 128, MTOT / 128), 256, HG_SMEM_BYTES>>>(
        b2hi, b2lo, w3hi, w3lo, b3, nullptr, nullptr, act1);

    // 4) mu head (fp32 scalar FFMA2) with output scatter
    mu_kernel<<<dim3(1, MTOT / 128), 256>>>(act1, muw, mub, out);
}

// round 10
// speedup vs baseline: 3.5334x; 1.8626x over previous
#include <cuda_runtime.h>
#include <cuda_bf16.h>
#include <math.h>
#include <stdint.h>

// Problem constants
#define BATCH   32
#define NW      16
#define BW      512
#define EMB     256
#define HID     512
#define OUTD    64
#define TSTEPS  128
#define MTOT    (BW * TSTEPS)

// ---------------------------------------------------------------------------
// Scratch (device globals)
// ---------------------------------------------------------------------------
__device__ float g_act1[(size_t)MTOT * HID];            // L3 fp32 out (mu input)
__device__ unsigned int g_bar;                          // GRU grid barrier

// h0 split (embedding output)
__device__ __nv_bfloat16 g_h0hi[BW * EMB];
__device__ __nv_bfloat16 g_h0lo[BW * EMB];
// bf16 split activations: slot t-1 holds h_t; doubles as MLP layer-1 A operand
__device__ __nv_bfloat16 g_a0hi[(size_t)MTOT * EMB];
__device__ __nv_bfloat16 g_a0lo[(size_t)MTOT * EMB];
__device__ __nv_bfloat16 g_b1hi[(size_t)MTOT * HID];
__device__ __nv_bfloat16 g_b1lo[(size_t)MTOT * HID];
__device__ __nv_bfloat16 g_b2hi[(size_t)MTOT * HID];
__device__ __nv_bfloat16 g_b2lo[(size_t)MTOT * HID];
// bf16 split weights
__device__ __nv_bfloat16 g_w1hi[HID * EMB], g_w1lo[HID * EMB];
__device__ __nv_bfloat16 g_w2hi[HID * HID], g_w2lo[HID * HID];
__device__ __nv_bfloat16 g_w3hi[HID * HID], g_w3lo[HID * HID];

// ---------------------------------------------------------------------------
// helpers
// ---------------------------------------------------------------------------
typedef unsigned long long ull;
__device__ __forceinline__ ull pack2(float x, float y) {
    ull r; asm("mov.b64 %0, {%1,%2};" : "=l"(r) : "f"(x), "f"(y)); return r;
}
__device__ __forceinline__ void ffma2(ull& d, ull a, ull b) {
    asm("fma.rn.f32x2 %0, %1, %2, %0;" : "+l"(d) : "l"(a), "l"(b));
}
__device__ __forceinline__ float2 unpk(ull v) {
    float2 f; asm("mov.b64 {%0,%1}, %2;" : "=f"(f.x), "=f"(f.y) : "l"(v)); return f;
}
__device__ __forceinline__ unsigned smaddr(const void* p) {
    unsigned r;
    asm("{.reg .u64 t; cvta.to.shared.u64 t, %1; cvt.u32.u64 %0, t;}"
        : "=r"(r) : "l"(p));
    return r;
}
#define CP16(ds, gs) asm volatile("cp.async.ca.shared.global [%0], [%1], 16;" :: "r"(ds), "l"(gs))
#define CPCOMMIT()   asm volatile("cp.async.commit_group;")
#define CPWAIT1()    asm volatile("cp.async.wait_group 1;" ::: "memory")
#define CPWAIT0()    asm volatile("cp.async.wait_group 0;" ::: "memory")

#define LDSM4(r, addr)                                                       \
    asm volatile("ldmatrix.sync.aligned.m8n8.x4.shared.b16 {%0,%1,%2,%3}, [%4];" \
        : "=r"((r)[0]), "=r"((r)[1]), "=r"((r)[2]), "=r"((r)[3]) : "r"(addr))

#define MMA16816(d, a, b0, b1)                                               \
    asm volatile("mma.sync.aligned.m16n8k16.row.col.f32.bf16.bf16.f32 "      \
        "{%0,%1,%2,%3}, {%4,%5,%6,%7}, {%8,%9}, {%0,%1,%2,%3};"              \
        : "+f"((d)[0]), "+f"((d)[1]), "+f"((d)[2]), "+f"((d)[3])             \
        : "r"((a)[0]), "r"((a)[1]), "r"((a)[2]), "r"((a)[3]),                \
          "r"(b0), "r"(b1))

__device__ __forceinline__ float sigm_fast(float x) {
    return __fdividef(1.f, 1.f + __expf(-x));
}
__device__ __forceinline__ float tanh_fast(float x) {
    float t = __expf(2.f * x);
    return 1.f - __fdividef(2.f, t + 1.f);
}

// ---------------------------------------------------------------------------
// Kernel 1: embedding -> h0 split [row][unit]. 4 rows/block (w_emb reuse x4).
// ---------------------------------------------------------------------------
__global__ __launch_bounds__(256) void embed_kernel(
        const float* __restrict__ z_t,
        const float* __restrict__ z_g,
        const float* __restrict__ w_emb) {
    __shared__ float zs[4][128];
    const int r0 = blockIdx.x * 4;
    const int u  = threadIdx.x;
    for (int i = u; i < 512; i += 256) {
        int row = i >> 7, c = i & 127;
        zs[row][c] = (c < 64) ? z_t[(r0 + row) * 64 + c]
                              : z_g[((r0 + row) >> 4) * 64 + (c - 64)];
    }
    __syncthreads();
    const float* wr = w_emb + u * 128;
    float acc[4] = {0.f, 0.f, 0.f, 0.f};
#pragma unroll 8
    for (int k = 0; k < 128; ++k) {
        float w = wr[k];
        acc[0] = fmaf(zs[0][k], w, acc[0]);
        acc[1] = fmaf(zs[1][k], w, acc[1]);
        acc[2] = fmaf(zs[2][k], w, acc[2]);
        acc[3] = fmaf(zs[3][k], w, acc[3]);
    }
#pragma unroll
    for (int r = 0; r < 4; ++r) {
        float v = acc[r];
        __nv_bfloat16 h = __float2bfloat16(v);
        g_h0hi[(r0 + r) * EMB + u] = h;
        g_h0lo[(r0 + r) * EMB + u] = __float2bfloat16(v - __bfloat162float(h));
    }
}

// ---------------------------------------------------------------------------
// Kernel W: split fp32 weights -> bf16 hi/lo
// ---------------------------------------------------------------------------
__global__ void wsplit_kernel(const float* __restrict__ w,
                              __nv_bfloat16* __restrict__ hi,
                              __nv_bfloat16* __restrict__ lo, int n) {
    int i = blockIdx.x * 256 + threadIdx.x;
    if (i < n) {
        float v = w[i];
        __nv_bfloat16 h = __float2bfloat16(v);
        hi[i] = h;
        lo[i] = __float2bfloat16(v - __bfloat162float(h));
    }
}

// ---------------------------------------------------------------------------
// Kernel 2: persistent HMMA GRU. 128 CTAs x 256 thr, 128 steps, one launch.
// CTA: units [u0, u0+8) x rows [r0, r0+128). Per step:
//   gates[128m x 24n] = h_prev[128 x 256] @ Whh_slice^T  (bf16 hi/lo split,
//   3 MMA products, fp32 accum). B rows ordered [r x8 | z x8 | n x8] so each
//   n8 tile = one gate and the gate update is thread-local (no shuffles).
// W slice resident in smem (split) all 128 steps; A streamed per step via
// double-buffered cp.async 64-k chunks. h stored ONLY as bf16 split in g_a0
// (slot t-1) = next step's A operand = MLP layer-1 input.
// smem: Whi[4kc][32r][128B] 16K | Wlo 16K | 2 A stages x (hi 16K + lo 16K).
// ---------------------------------------------------------------------------
#define GRU_SMEM_BYTES (32768 + 2 * 32768)

__global__ __launch_bounds__(256) void gru_persist_kernel(
        const float* __restrict__ w_hh,
        const float* __restrict__ b_ih,
        const float* __restrict__ b_hh) {
    extern __shared__ char smem[];
    const unsigned sbase = smaddr(smem);

    const int tid  = threadIdx.x;
    const int wid  = tid >> 5, lane = tid & 31;
    const int bx   = blockIdx.x;
    const int u0   = (bx >> 2) * 8;            // 32 unit blocks
    const int r0   = (bx & 3) * 128;           // 4 row blocks

    // ---- load + split W slice into smem ONCE ----
    for (int i = tid; i < 24 * 256; i += 256) {
        int gr = i >> 8;                       // gate-row 0..23
        int k  = i & 255;
        int g = gr >> 3, uu = gr & 7;
        float v = w_hh[(g * EMB + u0 + uu) * EMB + k];
        __nv_bfloat16 hv = __float2bfloat16(v);
        __nv_bfloat16 lv = __float2bfloat16(v - __bfloat162float(hv));
        int kc = k >> 6, kk = k & 63, cc = kk >> 3, e8 = kk & 7;
        unsigned off = (unsigned)(kc * 4096 + gr * 128 + ((cc ^ (gr & 7)) << 4) + e8 * 2);
        *(__nv_bfloat16*)(smem + off)         = hv;
        *(__nv_bfloat16*)(smem + 16384 + off) = lv;
    }

    // ---- per-thread epilogue constants ----
    const int grp = lane >> 2, q = lane & 3;
    float cr[2], cz[2], bnn[2], bin2[2];
#pragma unroll
    for (int e = 0; e < 2; ++e) {
        int j = u0 + 2 * q + e;
        cr[e]   = b_ih[j] + b_hh[j];
        cz[e]   = b_ih[EMB + j] + b_hh[EMB + j];
        bnn[e]  = b_hh[2 * EMB + j];
        bin2[e] = b_ih[2 * EMB + j];
    }

    // ldmatrix lane mapping
    const int seg = lane >> 3, lrow = lane & 7;
    const int rA  = wid * 16 + (seg & 1) * 8 + lrow;   // A rows (wid = m warp)
    const int rB1 = (seg & 1) * 8 + lrow;              // B rows 0..15 (r,z)
    const int rB2 = 16 + rB1;                          // B rows 16..31 (n,+pad)
    const int csel = seg >> 1;

    __syncthreads();

    for (int t = 1; t <= TSTEPS; ++t) {
        const __nv_bfloat16* phi =
            (t == 1) ? g_h0hi : g_a0hi + (size_t)(t - 2) * BW * EMB;
        const __nv_bfloat16* plo =
            (t == 1) ? g_h0lo : g_a0lo + (size_t)(t - 2) * BW * EMB;

        // A chunk loader (64 k per chunk, hi+lo)
        auto loadA = [&](int kc) {
            unsigned Ab = sbase + 32768 + (unsigned)((kc & 1) * 32768);
            int kbase = kc * 64;
#pragma unroll
            for (int it = 0; it < 8; ++it) {
                int i = tid + it * 256;        // 0..2047
                int buf = i >> 10;             // 0 hi, 1 lo
                int idx = i & 1023;
                int row = idx >> 3, cc = idx & 7;
                const __nv_bfloat16* src = buf ? plo : phi;
                unsigned sw = Ab + (unsigned)(buf * 16384 + row * 128 +
                                              ((cc ^ (row & 7)) << 4));
                CP16(sw, src + (size_t)(r0 + row) * EMB + kbase + cc * 8);
            }
            CPCOMMIT();
        };

        float acc[3][4];
#pragma unroll
        for (int g = 0; g < 3; ++g)
#pragma unroll
            for (int x = 0; x < 4; ++x) acc[g][x] = 0.f;

        loadA(0);
        for (int kc = 0; kc < 4; ++kc) {
            if (kc < 3) { loadA(kc + 1); CPWAIT1(); }
            else        { CPWAIT0(); }
            __syncthreads();

            unsigned Ab = sbase + 32768 + (unsigned)((kc & 1) * 32768);
            unsigned Wb = sbase + (unsigned)(kc * 4096);
#pragma unroll
            for (int s = 0; s < 4; ++s) {
                int kcc = s * 2 + csel;
                unsigned ah[4], al[4];
                unsigned aaddr = Ab + (unsigned)(rA * 128 + ((kcc ^ (rA & 7)) << 4));
                LDSM4(ah, aaddr);
                LDSM4(al, aaddr + 16384);
                unsigned bh1[4], bl1[4], bh2[4], bl2[4];
                unsigned b1a = Wb + (unsigned)(rB1 * 128 + ((kcc ^ (rB1 & 7)) << 4));
                unsigned b2a = Wb + (unsigned)(rB2 * 128 + ((kcc ^ (rB2 & 7)) << 4));
                LDSM4(bh1, b1a);
                LDSM4(bl1, b1a + 16384);
                LDSM4(bh2, b2a);
                LDSM4(bl2, b2a + 16384);
                // gate r (n8 tile 0: regs 0,2), z (tile 1: regs 1,3), n (tile 2)
                MMA16816(acc[0], ah, bh1[0], bh1[2]);
                MMA16816(acc[0], ah, bl1[0], bl1[2]);
                MMA16816(acc[0], al, bh1[0], bh1[2]);
                MMA16816(acc[1], ah, bh1[1], bh1[3]);
                MMA16816(acc[1], ah, bl1[1], bl1[3]);
                MMA16816(acc[1], al, bh1[1], bh1[3]);
                MMA16816(acc[2], ah, bh2[0], bh2[2]);
                MMA16816(acc[2], ah, bl2[0], bl2[2]);
                MMA16816(acc[2], al, bh2[0], bh2[2]);
            }
            __syncthreads();
        }

        // ---- epilogue: thread-local gate update, split, store ----
        __nv_bfloat16* dhi = g_a0hi + (size_t)(t - 1) * BW * EMB;
        __nv_bfloat16* dlo = g_a0lo + (size_t)(t - 1) * BW * EMB;
#pragma unroll
        for (int rh = 0; rh < 2; ++rh) {
            int m = r0 + wid * 16 + grp + rh * 8;
            size_t base = (size_t)m * EMB + u0 + 2 * q;
            __nv_bfloat162 hh = *(const __nv_bfloat162*)(phi + base);
            __nv_bfloat162 hl = *(const __nv_bfloat162*)(plo + base);
            float hp[2] = {__bfloat162float(hh.x) + __bfloat162float(hl.x),
                           __bfloat162float(hh.y) + __bfloat162float(hl.y)};
            float o[2];
#pragma unroll
            for (int e = 0; e < 2; ++e) {
                float r = sigm_fast(cr[e] + acc[0][rh * 2 + e]);
                float z = sigm_fast(cz[e] + acc[1][rh * 2 + e]);
                float n = tanh_fast(bin2[e] + r * (acc[2][rh * 2 + e] + bnn[e]));
                o[e] = (1.f - z) * n + z * hp[e];
            }
            __nv_bfloat162 oh, ol;
            oh.x = __float2bfloat16(o[0]);
            oh.y = __float2bfloat16(o[1]);
            ol.x = __float2bfloat16(o[0] - __bfloat162float(oh.x));
            ol.y = __float2bfloat16(o[1] - __bfloat162float(oh.y));
            *(__nv_bfloat162*)(dhi + base) = oh;
            *(__nv_bfloat162*)(dlo + base) = ol;
        }

        // ---- grid barrier (monotonic counter) ----
        __syncthreads();
        if (tid == 0) {
            __threadfence();
            atomicAdd(&g_bar, 1u);
            unsigned target = 128u * (unsigned)t;
            while (*(volatile unsigned*)&g_bar < target) { }
            __threadfence();
        }
        __syncthreads();
    }
}

// ---------------------------------------------------------------------------
// Kernel 3: HMMA split GEMM (proven R9). C = ELU(A@W^T + bias)
// ---------------------------------------------------------------------------
#define HG_SMEM_BYTES (512 + 2 * 4 * 16384)

template <int K, bool OUTBF16>
__global__ __launch_bounds__(256) void hmma_gemm_kernel(
        const __nv_bfloat16* __restrict__ Ahi, const __nv_bfloat16* __restrict__ Alo,
        const __nv_bfloat16* __restrict__ Whi, const __nv_bfloat16* __restrict__ Wlo,
        const float* __restrict__ bias,
        __nv_bfloat16* __restrict__ Chi, __nv_bfloat16* __restrict__ Clo,
        float* __restrict__ Cf) {
    constexpr int NC = K / 64;
    extern __shared__ char smem[];
    float* sbias = (float*)smem;
    const unsigned stile = smaddr(smem) + 512;

    const int tid  = threadIdx.x;
    const int wid  = tid >> 5, lane = tid & 31;
    const int wm   = wid & 3;
    const int wn   = wid >> 2;
    const int bn   = blockIdx.x * 128;
    const int bm   = blockIdx.y * 128;

    if (tid < 128) sbias[tid] = bias[bn + tid];

    auto load_chunk = [&](int c) {
        unsigned sb = stile + (unsigned)((c & 1) * 65536);
        int k0 = c * 64;
#pragma unroll
        for (int it = 0; it < 4; ++it) {
            int i = tid + it * 256;
            int row = i >> 3, cc = i & 7;
            unsigned sw = (unsigned)(row * 128 + ((cc ^ (row & 7)) << 4));
            size_t aoff = (size_t)(bm + row) * K + k0 + cc * 8;
            size_t woff = (size_t)(bn + row) * K + k0 + cc * 8;
            CP16(sb + sw,         Ahi + aoff);
            CP16(sb + 16384 + sw, Alo + aoff);
            CP16(sb + 32768 + sw, Whi + woff);
            CP16(sb + 49152 + sw, Wlo + woff);
        }
        CPCOMMIT();
    };

    float acc[2][8][4];
#pragma unroll
    for (int i = 0; i < 2; ++i)
#pragma unroll
        for (int j = 0; j < 8; ++j)
#pragma unroll
            for (int qd = 0; qd < 4; ++qd) acc[i][j][qd] = 0.f;

    const int seg  = lane >> 3, lrow = lane & 7;
    const int rA   = wm * 32 + (seg & 1) * 8 + lrow;
    const int rB   = wn * 64 + (seg & 1) * 8 + lrow;
    const int csel = seg >> 1;

    load_chunk(0);
    for (int c = 0; c < NC; ++c) {
        if (c + 1 < NC) { load_chunk(c + 1); CPWAIT1(); }
        else            { CPWAIT0(); }
        __syncthreads();
        unsigned sb = stile + (unsigned)((c & 1) * 65536);

#pragma unroll
        for (int s = 0; s < 4; ++s) {
            int kc = s * 2 + csel;
            unsigned ah[2][4], al[2][4];
#pragma unroll
            for (int ma = 0; ma < 2; ++ma) {
                int row = rA + ma * 16;
                unsigned addr = sb + (unsigned)(row * 128 + ((kc ^ (row & 7)) << 4));
                LDSM4(ah[ma], addr);
                LDSM4(al[ma], addr + 16384);
            }
            unsigned bh[4][4], bl[4][4];
#pragma unroll
            for (int ng = 0; ng < 4; ++ng) {
                int row = rB + ng * 16;
                unsigned addr = sb + 32768u +
                                (unsigned)(row * 128 + ((kc ^ (row & 7)) << 4));
                LDSM4(bh[ng], addr);
                LDSM4(bl[ng], addr + 16384);
            }
#pragma unroll
            for (int ma = 0; ma < 2; ++ma)
#pragma unroll
                for (int na = 0; na < 8; ++na) {
                    int ng = na >> 1, hf = na & 1;
                    MMA16816(acc[ma][na], ah[ma], bh[ng][hf], bh[ng][2 + hf]);
                    MMA16816(acc[ma][na], ah[ma], bl[ng][hf], bl[ng][2 + hf]);
                    MMA16816(acc[ma][na], al[ma], bh[ng][hf], bh[ng][2 + hf]);
                }
        }
        __syncthreads();
    }

    const int grp = lane >> 2, qid = lane & 3;
#pragma unroll
    for (int ma = 0; ma < 2; ++ma) {
#pragma unroll
        for (int na = 0; na < 8; ++na) {
            int col = wn * 64 + na * 8 + qid * 2;
            float b0v = sbias[col], b1v = sbias[col + 1];
#pragma unroll
            for (int hf = 0; hf < 2; ++hf) {
                int m = bm + wm * 32 + ma * 16 + grp + hf * 8;
                float v0 = acc[ma][na][hf * 2 + 0] + b0v;
                float v1 = acc[ma][na][hf * 2 + 1] + b1v;
                v0 = (v0 > 0.f) ? v0 : expm1f(v0);
                v1 = (v1 > 0.f) ? v1 : expm1f(v1);
                if (OUTBF16) {
                    __nv_bfloat162 h2, l2;
                    h2.x = __float2bfloat16(v0);
                    h2.y = __float2bfloat16(v1);
                    l2.x = __float2bfloat16(v0 - __bfloat162float(h2.x));
                    l2.y = __float2bfloat16(v1 - __bfloat162float(h2.y));
                    *(__nv_bfloat162*)(Chi + (size_t)m * HID + bn + col) = h2;
                    *(__nv_bfloat162*)(Clo + (size_t)m * HID + bn + col) = l2;
                } else {
                    *(float2*)(Cf + (size_t)m * HID + bn + col) =
                        make_float2(v0, v1);
                }
            }
        }
    }
}

// ---------------------------------------------------------------------------
// Kernel 4: scalar FFMA2 mu head (N=64, K=512), fp32 in, scatter out.
// ---------------------------------------------------------------------------
__global__ __launch_bounds__(256) void mu_kernel(
        const float* __restrict__ A,
        const float* __restrict__ Wt,
        const float* __restrict__ bias,
        float* __restrict__ C) {
    constexpr int BM = 128, BK = 16, BN = 64, TN = 4, TN2 = 2;
    constexpr int WS = BN + 4, WS4 = WS / 4;
    constexpr int K = HID;
    __shared__ float4 As4[BK * BM / 4];
    __shared__ float4 Ws4s[BK * WS4];
    float* As = (float*)As4;
    float* Ws = (float*)Ws4s;

    const int tid = threadIdx.x;
    const int tx  = tid & 15;
    const int ty  = tid >> 4;
    const int bm  = blockIdx.y * BM;

    ull acc2[8][TN2];
    {
        ull binit[TN2];
#pragma unroll
        for (int j = 0; j < TN2; ++j)
            binit[j] = pack2(bias[tx * TN + 2 * j], bias[tx * TN + 2 * j + 1]);
#pragma unroll
        for (int i = 0; i < 8; ++i)
#pragma unroll
            for (int j = 0; j < TN2; ++j) acc2[i][j] = binit[j];
    }

    for (int k0 = 0; k0 < K; k0 += BK) {
#pragma unroll
        for (int i = tid; i < 512; i += 256) {
            int row = i >> 2, kq = i & 3;
            float4 v = *(const float4*)(A + (size_t)(bm + row) * K + k0 + kq * 4);
            As[(kq * 4 + 0) * BM + row] = v.x;
            As[(kq * 4 + 1) * BM + row] = v.y;
            As[(kq * 4 + 2) * BM + row] = v.z;
            As[(kq * 4 + 3) * BM + row] = v.w;
        }
#pragma unroll
        for (int i = tid; i < BN * 4; i += 256) {
            int n = i >> 2, kq = i & 3;
            float4 v = *(const float4*)(Wt + (size_t)n * K + k0 + kq * 4);
            Ws[(kq * 4 + 0) * WS + n] = v.x;
            Ws[(kq * 4 + 1) * WS + n] = v.y;
            Ws[(kq * 4 + 2) * WS + n] = v.z;
            Ws[(kq * 4 + 3) * WS + n] = v.w;
        }
        __syncthreads();

#pragma unroll
        for (int k = 0; k < BK; ++k) {
            float4 a0 = As4[k * 32 + ty * 2];
            float4 a1 = As4[k * 32 + ty * 2 + 1];
            float av[8] = {a0.x, a0.y, a0.z, a0.w, a1.x, a1.y, a1.z, a1.w};
            const ull* bp = (const ull*)(Ws + k * WS + tx * TN);
            ull bv[TN2];
#pragma unroll
            for (int j = 0; j < TN2; ++j) bv[j] = bp[j];
#pragma unroll
            for (int i = 0; i < 8; ++i) {
                ull as2 = pack2(av[i], av[i]);
#pragma unroll
                for (int j = 0; j < TN2; ++j) ffma2(acc2[i][j], as2, bv[j]);
            }
        }
        __syncthreads();
    }

#pragma unroll
    for (int i = 0; i < 8; ++i) {
        int m = bm + ty * 8 + i;
        float o[TN];
#pragma unroll
        for (int j = 0; j < TN2; ++j) {
            float2 v = unpk(acc2[i][j]);
            o[2 * j] = v.x; o[2 * j + 1] = v.y;
        }
        int rowbw = m & 511, tt = m >> 9;
        float* dst = C + ((size_t)(rowbw * TSTEPS + tt)) * OUTD + tx * TN;
        *(float4*)dst = make_float4(o[0], o[1], o[2], o[3]);
    }
}

// ---------------------------------------------------------------------------
// Host launcher (graph-capturable)
// ---------------------------------------------------------------------------
extern "C" void kernel_launch(void* const* d_in, const int* in_sizes, int n_in,
                              void* d_out, int out_size) {
    (void)in_sizes; (void)n_in; (void)out_size;
    const float* z_t   = (const float*)d_in[0];
    const float* z_g   = (const float*)d_in[1];
    const float* w_emb = (const float*)d_in[2];
    const float* w_hh  = (const float*)d_in[3];
    const float* b_ih  = (const float*)d_in[4];
    const float* b_hh  = (const float*)d_in[5];
    const float* w1    = (const float*)d_in[6];
    const float* b1    = (const float*)d_in[7];
    const float* w2    = (const float*)d_in[8];
    const float* b2    = (const float*)d_in[9];
    const float* w3    = (const float*)d_in[10];
    const float* b3    = (const float*)d_in[11];
    const float* muw   = (const float*)d_in[12];
    const float* mub   = (const float*)d_in[13];
    float* out = (float*)d_out;

    float* act1;
    unsigned* barp;
    __nv_bfloat16 *a0hi, *a0lo, *b1hi, *b1lo, *b2hi, *b2lo;
    __nv_bfloat16 *w1hi, *w1lo, *w2hi, *w2lo, *w3hi, *w3lo;
    cudaGetSymbolAddress((void**)&act1, g_act1);
    cudaGetSymbolAddress((void**)&barp, g_bar);
    cudaGetSymbolAddress((void**)&a0hi, g_a0hi);
    cudaGetSymbolAddress((void**)&a0lo, g_a0lo);
    cudaGetSymbolAddress((void**)&b1hi, g_b1hi);
    cudaGetSymbolAddress((void**)&b1lo, g_b1lo);
    cudaGetSymbolAddress((void**)&b2hi, g_b2hi);
    cudaGetSymbolAddress((void**)&b2lo, g_b2lo);
    cudaGetSymbolAddress((void**)&w1hi, g_w1hi);
    cudaGetSymbolAddress((void**)&w1lo, g_w1lo);
    cudaGetSymbolAddress((void**)&w2hi, g_w2hi);
    cudaGetSymbolAddress((void**)&w2lo, g_w2lo);
    cudaGetSymbolAddress((void**)&w3hi, g_w3hi);
    cudaGetSymbolAddress((void**)&w3lo, g_w3lo);

    cudaFuncSetAttribute(gru_persist_kernel,
                         cudaFuncAttributeMaxDynamicSharedMemorySize, GRU_SMEM_BYTES);
    cudaFuncSetAttribute(hmma_gemm_kernel<EMB, true>,
                         cudaFuncAttributeMaxDynamicSharedMemorySize, HG_SMEM_BYTES);
    cudaFuncSetAttribute(hmma_gemm_kernel<HID, true>,
                         cudaFuncAttributeMaxDynamicSharedMemorySize, HG_SMEM_BYTES);
    cudaFuncSetAttribute(hmma_gemm_kernel<HID, false>,
                         cudaFuncAttributeMaxDynamicSharedMemorySize, HG_SMEM_BYTES);

    cudaMemsetAsync(barp, 0, sizeof(unsigned));

    // weight splits
    wsplit_kernel<<<(HID * EMB + 255) / 256, 256>>>(w1, w1hi, w1lo, HID * EMB);
    wsplit_kernel<<<(HID * HID + 255) / 256, 256>>>(w2, w2hi, w2lo, HID * HID);
    wsplit_kernel<<<(HID * HID + 255) / 256, 256>>>(w3, w3hi, w3lo, HID * HID);

    // 1) embedding -> h0 split
    embed_kernel<<<128, 256>>>(z_t, z_g, w_emb);

    // 2) persistent HMMA GRU (writes bf16 split h into g_a0 slots 0..127)
    gru_persist_kernel<<<128, 256, GRU_SMEM_BYTES>>>(w_hh, b_ih, b_hh);

    // 3) MLP on tensor cores (bf16-split, fp32 accum)
    hmma_gemm_kernel<EMB, true><<<dim3(HID / 128, MTOT / 128), 256, HG_SMEM_BYTES>>>(
        a0hi, a0lo, w1hi, w1lo, b1, b1hi, b1lo, nullptr);
    hmma_gemm_kernel<HID, true><<<dim3(HID / 128, MTOT / 128), 256, HG_SMEM_BYTES>>>(
        b1hi, b1lo, w2hi, w2lo, b2, b2hi, b2lo, nullptr);
    hmma_gemm_kernel<HID, false><<<dim3(HID / 128, MTOT / 128), 256, HG_SMEM_BYTES>>>(
        b2hi, b2lo, w3hi, w3lo, b3, nullptr, nullptr, act1);

    // 4) mu head (fp32 scalar FFMA2) with output scatter
    mu_kernel<<<dim3(1, MTOT / 128), 256>>>(act1, muw, mub, out);
}

// round 13
// speedup vs baseline: 3.6721x; 1.0393x over previous
#include <cuda_runtime.h>
#include <cuda_bf16.h>
#include <math.h>
#include <stdint.h>

// Problem constants
#define BATCH   32
#define NW      16
#define BW      512
#define EMB     256
#define HID     512
#define OUTD    64
#define TSTEPS  128
#define MTOT    (BW * TSTEPS)

// ---------------------------------------------------------------------------
// Scratch (device globals)
// ---------------------------------------------------------------------------
__device__ unsigned int g_bar;                          // GRU grid barrier

// h0 split (embedding output)
__device__ __nv_bfloat16 g_h0hi[BW * EMB];
__device__ __nv_bfloat16 g_h0lo[BW * EMB];
// bf16 split activations: slot t-1 holds h_t; doubles as MLP layer-1 A operand
__device__ __nv_bfloat16 g_a0hi[(size_t)MTOT * EMB];
__device__ __nv_bfloat16 g_a0lo[(size_t)MTOT * EMB];
__device__ __nv_bfloat16 g_b1hi[(size_t)MTOT * HID];    // L1 out; reused as L3 out
__device__ __nv_bfloat16 g_b1lo[(size_t)MTOT * HID];
__device__ __nv_bfloat16 g_b2hi[(size_t)MTOT * HID];
__device__ __nv_bfloat16 g_b2lo[(size_t)MTOT * HID];
// bf16 split weights
__device__ __nv_bfloat16 g_w1hi[HID * EMB], g_w1lo[HID * EMB];
__device__ __nv_bfloat16 g_w2hi[HID * HID], g_w2lo[HID * HID];
__device__ __nv_bfloat16 g_w3hi[HID * HID], g_w3lo[HID * HID];
__device__ __nv_bfloat16 g_wmhi[OUTD * HID], g_wmlo[OUTD * HID];

// ---------------------------------------------------------------------------
// helpers
// ---------------------------------------------------------------------------
__device__ __forceinline__ unsigned smaddr(const void* p) {
    unsigned r;
    asm("{.reg .u64 t; cvta.to.shared.u64 t, %1; cvt.u32.u64 %0, t;}"
        : "=r"(r) : "l"(p));
    return r;
}
#define CP16(ds, gs) asm volatile("cp.async.ca.shared.global [%0], [%1], 16;" :: "r"(ds), "l"(gs))
#define CPCOMMIT()   asm volatile("cp.async.commit_group;")
#define CPWAIT1()    asm volatile("cp.async.wait_group 1;" ::: "memory")
#define CPWAIT0()    asm volatile("cp.async.wait_group 0;" ::: "memory")

#define LDSM4(r, addr)                                                       \
    asm volatile("ldmatrix.sync.aligned.m8n8.x4.shared.b16 {%0,%1,%2,%3}, [%4];" \
        : "=r"((r)[0]), "=r"((r)[1]), "=r"((r)[2]), "=r"((r)[3]) : "r"(addr))

#define MMA16816(d, a, b0, b1)                                               \
    asm volatile("mma.sync.aligned.m16n8k16.row.col.f32.bf16.bf16.f32 "      \
        "{%0,%1,%2,%3}, {%4,%5,%6,%7}, {%8,%9}, {%0,%1,%2,%3};"              \
        : "+f"((d)[0]), "+f"((d)[1]), "+f"((d)[2]), "+f"((d)[3])             \
        : "r"((a)[0]), "r"((a)[1]), "r"((a)[2]), "r"((a)[3]),                \
          "r"(b0), "r"(b1))

__device__ __forceinline__ float sigm_fast(float x) {
    return __fdividef(1.f, 1.f + __expf(-x));
}
__device__ __forceinline__ float tanh_fast(float x) {
    float t = __expf(2.f * x);
    return 1.f - __fdividef(2.f, t + 1.f);
}

// ---------------------------------------------------------------------------
// Kernel 1: embedding -> h0 split [row][unit]. 4 rows/block. (proven R10)
// ---------------------------------------------------------------------------
__global__ __launch_bounds__(256) void embed_kernel(
        const float* __restrict__ z_t,
        const float* __restrict__ z_g,
        const float* __restrict__ w_emb) {
    __shared__ float zs[4][128];
    const int r0 = blockIdx.x * 4;
    const int u  = threadIdx.x;
    for (int i = u; i < 512; i += 256) {
        int row = i >> 7, c = i & 127;
        zs[row][c] = (c < 64) ? z_t[(r0 + row) * 64 + c]
                              : z_g[((r0 + row) >> 4) * 64 + (c - 64)];
    }
    __syncthreads();
    const float* wr = w_emb + u * 128;
    float acc[4] = {0.f, 0.f, 0.f, 0.f};
#pragma unroll 8
    for (int k = 0; k < 128; ++k) {
        float w = wr[k];
        acc[0] = fmaf(zs[0][k], w, acc[0]);
        acc[1] = fmaf(zs[1][k], w, acc[1]);
        acc[2] = fmaf(zs[2][k], w, acc[2]);
        acc[3] = fmaf(zs[3][k], w, acc[3]);
    }
#pragma unroll
    for (int r = 0; r < 4; ++r) {
        float v = acc[r];
        __nv_bfloat16 h = __float2bfloat16(v);
        g_h0hi[(r0 + r) * EMB + u] = h;
        g_h0lo[(r0 + r) * EMB + u] = __float2bfloat16(v - __bfloat162float(h));
    }
}

// ---------------------------------------------------------------------------
// Kernel W: split fp32 weights -> bf16 hi/lo
// ---------------------------------------------------------------------------
__global__ void wsplit_kernel(const float* __restrict__ w,
                              __nv_bfloat16* __restrict__ hi,
                              __nv_bfloat16* __restrict__ lo, int n) {
    int i = blockIdx.x * 256 + threadIdx.x;
    if (i < n) {
        float v = w[i];
        __nv_bfloat16 h = __float2bfloat16(v);
        hi[i] = h;
        lo[i] = __float2bfloat16(v - __bfloat162float(h));
    }
}

// ---------------------------------------------------------------------------
// Kernel 2: persistent HMMA GRU (proven R10, unchanged).
// ---------------------------------------------------------------------------
#define GRU_SMEM_BYTES (32768 + 2 * 32768)

__global__ __launch_bounds__(256) void gru_persist_kernel(
        const float* __restrict__ w_hh,
        const float* __restrict__ b_ih,
        const float* __restrict__ b_hh) {
    extern __shared__ char smem[];
    const unsigned sbase = smaddr(smem);

    const int tid  = threadIdx.x;
    const int wid  = tid >> 5, lane = tid & 31;
    const int bx   = blockIdx.x;
    const int u0   = (bx >> 2) * 8;
    const int r0   = (bx & 3) * 128;

    for (int i = tid; i < 24 * 256; i += 256) {
        int gr = i >> 8;
        int k  = i & 255;
        int g = gr >> 3, uu = gr & 7;
        float v = w_hh[(g * EMB + u0 + uu) * EMB + k];
        __nv_bfloat16 hv = __float2bfloat16(v);
        __nv_bfloat16 lv = __float2bfloat16(v - __bfloat162float(hv));
        int kc = k >> 6, kk = k & 63, cc = kk >> 3, e8 = kk & 7;
        unsigned off = (unsigned)(kc * 4096 + gr * 128 + ((cc ^ (gr & 7)) << 4) + e8 * 2);
        *(__nv_bfloat16*)(smem + off)         = hv;
        *(__nv_bfloat16*)(smem + 16384 + off) = lv;
    }

    const int grp = lane >> 2, q = lane & 3;
    float cr[2], cz[2], bnn[2], bin2[2];
#pragma unroll
    for (int e = 0; e < 2; ++e) {
        int j = u0 + 2 * q + e;
        cr[e]   = b_ih[j] + b_hh[j];
        cz[e]   = b_ih[EMB + j] + b_hh[EMB + j];
        bnn[e]  = b_hh[2 * EMB + j];
        bin2[e] = b_ih[2 * EMB + j];
    }

    const int seg = lane >> 3, lrow = lane & 7;
    const int rA  = wid * 16 + (seg & 1) * 8 + lrow;
    const int rB1 = (seg & 1) * 8 + lrow;
    const int rB2 = 16 + rB1;
    const int csel = seg >> 1;

    __syncthreads();

    for (int t = 1; t <= TSTEPS; ++t) {
        const __nv_bfloat16* phi =
            (t == 1) ? g_h0hi : g_a0hi + (size_t)(t - 2) * BW * EMB;
        const __nv_bfloat16* plo =
            (t == 1) ? g_h0lo : g_a0lo + (size_t)(t - 2) * BW * EMB;

        auto loadA = [&](int kc) {
            unsigned Ab = sbase + 32768 + (unsigned)((kc & 1) * 32768);
            int kbase = kc * 64;
#pragma unroll
            for (int it = 0; it < 8; ++it) {
                int i = tid + it * 256;
                int buf = i >> 10;
                int idx = i & 1023;
                int row = idx >> 3, cc = idx & 7;
                const __nv_bfloat16* src = buf ? plo : phi;
                unsigned sw = Ab + (unsigned)(buf * 16384 + row * 128 +
                                              ((cc ^ (row & 7)) << 4));
                CP16(sw, src + (size_t)(r0 + row) * EMB + kbase + cc * 8);
            }
            CPCOMMIT();
        };

        float acc[3][4];
#pragma unroll
        for (int g = 0; g < 3; ++g)
#pragma unroll
            for (int x = 0; x < 4; ++x) acc[g][x] = 0.f;

        loadA(0);
        for (int kc = 0; kc < 4; ++kc) {
            if (kc < 3) { loadA(kc + 1); CPWAIT1(); }
            else        { CPWAIT0(); }
            __syncthreads();

            unsigned Ab = sbase + 32768 + (unsigned)((kc & 1) * 32768);
            unsigned Wb = sbase + (unsigned)(kc * 4096);
#pragma unroll
            for (int s = 0; s < 4; ++s) {
                int kcc = s * 2 + csel;
                unsigned ah[4], al[4];
                unsigned aaddr = Ab + (unsigned)(rA * 128 + ((kcc ^ (rA & 7)) << 4));
                LDSM4(ah, aaddr);
                LDSM4(al, aaddr + 16384);
                unsigned bh1[4], bl1[4], bh2[4], bl2[4];
                unsigned b1a = Wb + (unsigned)(rB1 * 128 + ((kcc ^ (rB1 & 7)) << 4));
                unsigned b2a = Wb + (unsigned)(rB2 * 128 + ((kcc ^ (rB2 & 7)) << 4));
                LDSM4(bh1, b1a);
                LDSM4(bl1, b1a + 16384);
                LDSM4(bh2, b2a);
                LDSM4(bl2, b2a + 16384);
                MMA16816(acc[0], ah, bh1[0], bh1[2]);
                MMA16816(acc[0], ah, bl1[0], bl1[2]);
                MMA16816(acc[0], al, bh1[0], bh1[2]);
                MMA16816(acc[1], ah, bh1[1], bh1[3]);
                MMA16816(acc[1], ah, bl1[1], bl1[3]);
                MMA16816(acc[1], al, bh1[1], bh1[3]);
                MMA16816(acc[2], ah, bh2[0], bh2[2]);
                MMA16816(acc[2], ah, bl2[0], bl2[2]);
                MMA16816(acc[2], al, bh2[0], bh2[2]);
            }
            __syncthreads();
        }

        __nv_bfloat16* dhi = g_a0hi + (size_t)(t - 1) * BW * EMB;
        __nv_bfloat16* dlo = g_a0lo + (size_t)(t - 1) * BW * EMB;
#pragma unroll
        for (int rh = 0; rh < 2; ++rh) {
            int m = r0 + wid * 16 + grp + rh * 8;
            size_t base = (size_t)m * EMB + u0 + 2 * q;
            __nv_bfloat162 hh = *(const __nv_bfloat162*)(phi + base);
            __nv_bfloat162 hl = *(const __nv_bfloat162*)(plo + base);
            float hp[2] = {__bfloat162float(hh.x) + __bfloat162float(hl.x),
                           __bfloat162float(hh.y) + __bfloat162float(hl.y)};
            float o[2];
#pragma unroll
            for (int e = 0; e < 2; ++e) {
                float r = sigm_fast(cr[e] + acc[0][rh * 2 + e]);
                float z = sigm_fast(cz[e] + acc[1][rh * 2 + e]);
                float n = tanh_fast(bin2[e] + r * (acc[2][rh * 2 + e] + bnn[e]));
                o[e] = (1.f - z) * n + z * hp[e];
            }
            __nv_bfloat162 oh, ol;
            oh.x = __float2bfloat16(o[0]);
            oh.y = __float2bfloat16(o[1]);
            ol.x = __float2bfloat16(o[0] - __bfloat162float(oh.x));
            ol.y = __float2bfloat16(o[1] - __bfloat162float(oh.y));
            *(__nv_bfloat162*)(dhi + base) = oh;
            *(__nv_bfloat162*)(dlo + base) = ol;
        }

        __syncthreads();
        if (tid == 0) {
            __threadfence();
            atomicAdd(&g_bar, 1u);
            unsigned target = 128u * (unsigned)t;
            while (*(volatile unsigned*)&g_bar < target) { }
            __threadfence();
        }
        __syncthreads();
    }
}

// ---------------------------------------------------------------------------
// Kernel 3: HMMA split GEMM, 2-stage pipeline (EXACT proven R10 version).
// ---------------------------------------------------------------------------
#define HG_SMEM_BYTES (512 + 2 * 4 * 16384)

template <int K, bool OUTBF16>
__global__ __launch_bounds__(256) void hmma_gemm_kernel(
        const __nv_bfloat16* __restrict__ Ahi, const __nv_bfloat16* __restrict__ Alo,
        const __nv_bfloat16* __restrict__ Whi, const __nv_bfloat16* __restrict__ Wlo,
        const float* __restrict__ bias,
        __nv_bfloat16* __restrict__ Chi, __nv_bfloat16* __restrict__ Clo,
        float* __restrict__ Cf) {
    constexpr int NC = K / 64;
    extern __shared__ char smem[];
    float* sbias = (float*)smem;
    const unsigned stile = smaddr(smem) + 512;

    const int tid  = threadIdx.x;
    const int wid  = tid >> 5, lane = tid & 31;
    const int wm   = wid & 3;
    const int wn   = wid >> 2;
    const int bn   = blockIdx.x * 128;
    const int bm   = blockIdx.y * 128;

    if (tid < 128) sbias[tid] = bias[bn + tid];

    auto load_chunk = [&](int c) {
        unsigned sb = stile + (unsigned)((c & 1) * 65536);
        int k0 = c * 64;
#pragma unroll
        for (int it = 0; it < 4; ++it) {
            int i = tid + it * 256;
            int row = i >> 3, cc = i & 7;
            unsigned sw = (unsigned)(row * 128 + ((cc ^ (row & 7)) << 4));
            size_t aoff = (size_t)(bm + row) * K + k0 + cc * 8;
            size_t woff = (size_t)(bn + row) * K + k0 + cc * 8;
            CP16(sb + sw,         Ahi + aoff);
            CP16(sb + 16384 + sw, Alo + aoff);
            CP16(sb + 32768 + sw, Whi + woff);
            CP16(sb + 49152 + sw, Wlo + woff);
        }
        CPCOMMIT();
    };

    float acc[2][8][4];
#pragma unroll
    for (int i = 0; i < 2; ++i)
#pragma unroll
        for (int j = 0; j < 8; ++j)
#pragma unroll
            for (int qd = 0; qd < 4; ++qd) acc[i][j][qd] = 0.f;

    const int seg  = lane >> 3, lrow = lane & 7;
    const int rA   = wm * 32 + (seg & 1) * 8 + lrow;
    const int rB   = wn * 64 + (seg & 1) * 8 + lrow;
    const int csel = seg >> 1;

    load_chunk(0);
    for (int c = 0; c < NC; ++c) {
        if (c + 1 < NC) { load_chunk(c + 1); CPWAIT1(); }
        else            { CPWAIT0(); }
        __syncthreads();
        unsigned sb = stile + (unsigned)((c & 1) * 65536);

#pragma unroll
        for (int s = 0; s < 4; ++s) {
            int kc = s * 2 + csel;
            unsigned ah[2][4], al[2][4];
#pragma unroll
            for (int ma = 0; ma < 2; ++ma) {
                int row = rA + ma * 16;
                unsigned addr = sb + (unsigned)(row * 128 + ((kc ^ (row & 7)) << 4));
                LDSM4(ah[ma], addr);
                LDSM4(al[ma], addr + 16384);
            }
            unsigned bh[4][4], bl[4][4];
#pragma unroll
            for (int ng = 0; ng < 4; ++ng) {
                int row = rB + ng * 16;
                unsigned addr = sb + 32768u +
                                (unsigned)(row * 128 + ((kc ^ (row & 7)) << 4));
                LDSM4(bh[ng], addr);
                LDSM4(bl[ng], addr + 16384);
            }
#pragma unroll
            for (int ma = 0; ma < 2; ++ma)
#pragma unroll
                for (int na = 0; na < 8; ++na) {
                    int ng = na >> 1, hf = na & 1;
                    MMA16816(acc[ma][na], ah[ma], bh[ng][hf], bh[ng][2 + hf]);
                    MMA16816(acc[ma][na], ah[ma], bl[ng][hf], bl[ng][2 + hf]);
                    MMA16816(acc[ma][na], al[ma], bh[ng][hf], bh[ng][2 + hf]);
                }
        }
        __syncthreads();
    }

    const int grp = lane >> 2, qid = lane & 3;
#pragma unroll
    for (int ma = 0; ma < 2; ++ma) {
#pragma unroll
        for (int na = 0; na < 8; ++na) {
            int col = wn * 64 + na * 8 + qid * 2;
            float b0v = sbias[col], b1v = sbias[col + 1];
#pragma unroll
            for (int hf = 0; hf < 2; ++hf) {
                int m = bm + wm * 32 + ma * 16 + grp + hf * 8;
                float v0 = acc[ma][na][hf * 2 + 0] + b0v;
                float v1 = acc[ma][na][hf * 2 + 1] + b1v;
                v0 = (v0 > 0.f) ? v0 : expm1f(v0);
                v1 = (v1 > 0.f) ? v1 : expm1f(v1);
                if (OUTBF16) {
                    __nv_bfloat162 h2, l2;
                    h2.x = __float2bfloat16(v0);
                    h2.y = __float2bfloat16(v1);
                    l2.x = __float2bfloat16(v0 - __bfloat162float(h2.x));
                    l2.y = __float2bfloat16(v1 - __bfloat162float(h2.y));
                    *(__nv_bfloat162*)(Chi + (size_t)m * HID + bn + col) = h2;
                    *(__nv_bfloat162*)(Clo + (size_t)m * HID + bn + col) = l2;
                } else {
                    *(float2*)(Cf + (size_t)m * HID + bn + col) =
                        make_float2(v0, v1);
                }
            }
        }
    }
}

// ---------------------------------------------------------------------------
// Kernel 4: HMMA mu head, 2-stage pipeline (same skeleton as proven GEMM).
// out = A @ muw^T + bias, scattered to (B, W*T, OUT).
// Tile 128m x 64n, 8 m-warps, K=512.
// smem stage: Ahi 16K | Alo 16K | Whi 8K | Wlo 8K = 48KB; x2 stages.
// ---------------------------------------------------------------------------
#define MU_SMEM_BYTES (256 + 2 * 49152)

__global__ __launch_bounds__(256) void mu_hmma_kernel(
        const __nv_bfloat16* __restrict__ Ahi, const __nv_bfloat16* __restrict__ Alo,
        const __nv_bfloat16* __restrict__ Whi, const __nv_bfloat16* __restrict__ Wlo,
        const float* __restrict__ bias,
        float* __restrict__ out) {
    constexpr int K = HID, NC = K / 64;
    extern __shared__ char smem[];
    float* sbias = (float*)smem;
    const unsigned stile = smaddr(smem) + 256;

    const int tid  = threadIdx.x;
    const int wid  = tid >> 5, lane = tid & 31;
    const int bm   = blockIdx.y * 128;

    if (tid < 64) sbias[tid] = bias[tid];

    auto load_chunk = [&](int c) {
        unsigned sb = stile + (unsigned)((c & 1) * 49152);
        int k0 = c * 64;
        // A tiles (hi+lo): 128 rows x 64 k
#pragma unroll
        for (int it = 0; it < 8; ++it) {
            int i = tid + it * 256;
            int buf = i >> 10, idx = i & 1023;
            int row = idx >> 3, cc = idx & 7;
            const __nv_bfloat16* src = buf ? Alo : Ahi;
            unsigned sw = sb + (unsigned)(buf * 16384 + row * 128 +
                                          ((cc ^ (row & 7)) << 4));
            CP16(sw, src + (size_t)(bm + row) * K + k0 + cc * 8);
        }
        // W tiles (hi+lo): 64 rows x 64 k
#pragma unroll
        for (int it = 0; it < 4; ++it) {
            int i = tid + it * 256;
            int buf = i >> 9, idx = i & 511;
            int row = idx >> 3, cc = idx & 7;
            const __nv_bfloat16* src = buf ? Wlo : Whi;
            unsigned sw = sb + 32768u + (unsigned)(buf * 8192 + row * 128 +
                                                   ((cc ^ (row & 7)) << 4));
            CP16(sw, src + (size_t)row * K + k0 + cc * 8);
        }
        CPCOMMIT();
    };

    float acc[8][4];
#pragma unroll
    for (int j = 0; j < 8; ++j)
#pragma unroll
        for (int qd = 0; qd < 4; ++qd) acc[j][qd] = 0.f;

    const int seg  = lane >> 3, lrow = lane & 7;
    const int rA   = wid * 16 + (seg & 1) * 8 + lrow;
    const int rB   = (seg & 1) * 8 + lrow;
    const int csel = seg >> 1;

    load_chunk(0);
    for (int c = 0; c < NC; ++c) {
        if (c + 1 < NC) { load_chunk(c + 1); CPWAIT1(); }
        else            { CPWAIT0(); }
        __syncthreads();
        unsigned sb = stile + (unsigned)((c & 1) * 49152);

#pragma unroll
        for (int s = 0; s < 4; ++s) {
            int kc = s * 2 + csel;
            unsigned ah[4], al[4];
            unsigned aaddr = sb + (unsigned)(rA * 128 + ((kc ^ (rA & 7)) << 4));
            LDSM4(ah, aaddr);
            LDSM4(al, aaddr + 16384);
            unsigned bh[4][4], bl[4][4];
#pragma unroll
            for (int ng = 0; ng < 4; ++ng) {
                int row = rB + ng * 16;
                unsigned addr = sb + 32768u +
                                (unsigned)(row * 128 + ((kc ^ (row & 7)) << 4));
                LDSM4(bh[ng], addr);
                LDSM4(bl[ng], addr + 8192);
            }
#pragma unroll
            for (int na = 0; na < 8; ++na) {
                int ng = na >> 1, hf = na & 1;
                MMA16816(acc[na], ah, bh[ng][hf], bh[ng][2 + hf]);
                MMA16816(acc[na], ah, bl[ng][hf], bl[ng][2 + hf]);
                MMA16816(acc[na], al, bh[ng][hf], bh[ng][2 + hf]);
            }
        }
        __syncthreads();
    }

    const int grp = lane >> 2, qid = lane & 3;
#pragma unroll
    for (int na = 0; na < 8; ++na) {
        int col = na * 8 + qid * 2;
        float b0v = sbias[col], b1v = sbias[col + 1];
#pragma unroll
        for (int hf = 0; hf < 2; ++hf) {
            int m = bm + wid * 16 + grp + hf * 8;
            float v0 = acc[na][hf * 2 + 0] + b0v;
            float v1 = acc[na][hf * 2 + 1] + b1v;
            int rowbw = m & 511, tt = m >> 9;
            *(float2*)(out + ((size_t)(rowbw * TSTEPS + tt)) * OUTD + col) =
                make_float2(v0, v1);
        }
    }
}

// ---------------------------------------------------------------------------
// Host launcher (graph-capturable)
// ---------------------------------------------------------------------------
extern "C" void kernel_launch(void* const* d_in, const int* in_sizes, int n_in,
                              void* d_out, int out_size) {
    (void)in_sizes; (void)n_in; (void)out_size;
    const float* z_t   = (const float*)d_in[0];
    const float* z_g   = (const float*)d_in[1];
    const float* w_emb = (const float*)d_in[2];
    const float* w_hh  = (const float*)d_in[3];
    const float* b_ih  = (const float*)d_in[4];
    const float* b_hh  = (const float*)d_in[5];
    const float* w1    = (const float*)d_in[6];
    const float* b1    = (const float*)d_in[7];
    const float* w2    = (const float*)d_in[8];
    const float* b2    = (const float*)d_in[9];
    const float* w3    = (const float*)d_in[10];
    const float* b3    = (const float*)d_in[11];
    const float* muw   = (const float*)d_in[12];
    const float* mub   = (const float*)d_in[13];
    float* out = (float*)d_out;

    unsigned* barp;
    __nv_bfloat16 *a0hi, *a0lo, *b1hi, *b1lo, *b2hi, *b2lo;
    __nv_bfloat16 *w1hi, *w1lo, *w2hi, *w2lo, *w3hi, *w3lo, *wmhi, *wmlo;
    cudaGetSymbolAddress((void**)&barp, g_bar);
    cudaGetSymbolAddress((void**)&a0hi, g_a0hi);
    cudaGetSymbolAddress((void**)&a0lo, g_a0lo);
    cudaGetSymbolAddress((void**)&b1hi, g_b1hi);
    cudaGetSymbolAddress((void**)&b1lo, g_b1lo);
    cudaGetSymbolAddress((void**)&b2hi, g_b2hi);
    cudaGetSymbolAddress((void**)&b2lo, g_b2lo);
    cudaGetSymbolAddress((void**)&w1hi, g_w1hi);
    cudaGetSymbolAddress((void**)&w1lo, g_w1lo);
    cudaGetSymbolAddress((void**)&w2hi, g_w2hi);
    cudaGetSymbolAddress((void**)&w2lo, g_w2lo);
    cudaGetSymbolAddress((void**)&w3hi, g_w3hi);
    cudaGetSymbolAddress((void**)&w3lo, g_w3lo);
    cudaGetSymbolAddress((void**)&wmhi, g_wmhi);
    cudaGetSymbolAddress((void**)&wmlo, g_wmlo);

    cudaFuncSetAttribute(gru_persist_kernel,
                         cudaFuncAttributeMaxDynamicSharedMemorySize, GRU_SMEM_BYTES);
    cudaFuncSetAttribute(hmma_gemm_kernel<EMB, true>,
                         cudaFuncAttributeMaxDynamicSharedMemorySize, HG_SMEM_BYTES);
    cudaFuncSetAttribute(hmma_gemm_kernel<HID, true>,
                         cudaFuncAttributeMaxDynamicSharedMemorySize, HG_SMEM_BYTES);
    cudaFuncSetAttribute(mu_hmma_kernel,
                         cudaFuncAttributeMaxDynamicSharedMemorySize, MU_SMEM_BYTES);

    cudaMemsetAsync(barp, 0, sizeof(unsigned));

    // weight splits
    wsplit_kernel<<<(HID * EMB + 255) / 256, 256>>>(w1, w1hi, w1lo, HID * EMB);
    wsplit_kernel<<<(HID * HID + 255) / 256, 256>>>(w2, w2hi, w2lo, HID * HID);
    wsplit_kernel<<<(HID * HID + 255) / 256, 256>>>(w3, w3hi, w3lo, HID * HID);
    wsplit_kernel<<<(OUTD * HID + 255) / 256, 256>>>(muw, wmhi, wmlo, OUTD * HID);

    // 1) embedding -> h0 split
    embed_kernel<<<128, 256>>>(z_t, z_g, w_emb);

    // 2) persistent HMMA GRU (writes bf16 split h into g_a0 slots 0..127)
    gru_persist_kernel<<<128, 256, GRU_SMEM_BYTES>>>(w_hh, b_ih, b_hh);

    // 3) MLP on tensor cores (bf16-split, fp32 accum); L3 reuses b1 buffers
    hmma_gemm_kernel<EMB, true><<<dim3(HID / 128, MTOT / 128), 256, HG_SMEM_BYTES>>>(
        a0hi, a0lo, w1hi, w1lo, b1, b1hi, b1lo, nullptr);
    hmma_gemm_kernel<HID, true><<<dim3(HID / 128, MTOT / 128), 256, HG_SMEM_BYTES>>>(
        b1hi, b1lo, w2hi, w2lo, b2, b2hi, b2lo, nullptr);
    hmma_gemm_kernel<HID, true><<<dim3(HID / 128, MTOT / 128), 256, HG_SMEM_BYTES>>>(
        b2hi, b2lo, w3hi, w3lo, b3, b1hi, b1lo, nullptr);

    // 4) HMMA mu head with output scatter
    mu_hmma_kernel<<<dim3(1, MTOT / 128), 256, MU_SMEM_BYTES>>>(
        b1hi, b1lo, wmhi, wmlo, mub, out);
}